// round 2
// baseline (speedup 1.0000x reference)
#include <cuda_runtime.h>
#include <cuda_bf16.h>
#include <math.h>

// Problem constants (fixed by the dataset)
#define BB 8
#define LL 4096
#define DD 768
#define HH 512
#define NTOK (BB * LL)          // 32768
#define POOLED_ELEMS (BB * LL * DD)

// Device scratch (no allocations allowed)
__device__ float         g_logits[NTOK];
__device__ unsigned char g_hard[NTOK];
__device__ int           g_seg[NTOK];
__device__ int           g_bcnt[BB];

// ---------------------------------------------------------------------------
// K0: zero the pooled region of d_out
// ---------------------------------------------------------------------------
__global__ void zero_kernel(float4* out, int n4) {
    int i = blockIdx.x * blockDim.x + threadIdx.x;
    int stride = gridDim.x * blockDim.x;
    float4 z = make_float4(0.f, 0.f, 0.f, 0.f);
    for (; i < n4; i += stride) out[i] = z;
}

// ---------------------------------------------------------------------------
// K1: fused logits GEMM: logits[m] = sum_n relu(sum_k X[m,k]*W1[k,n] + b1[n]) * W2[n] + b2
// Tile: 64 tokens x 64 n-cols, TK=16, 8 n-chunks per block, 256 threads (16x16),
// 4x4 micro-tile per thread.
// ---------------------------------------------------------------------------
__global__ __launch_bounds__(256) void gemm_logits_kernel(
    const float* __restrict__ X,   // [NTOK, DD]
    const float* __restrict__ W1,  // [DD, HH]
    const float* __restrict__ b1,  // [HH]
    const float* __restrict__ W2,  // [HH]
    const float* __restrict__ b2)  // [1]
{
    __shared__ float As[16][68];       // [k][m], padded
    __shared__ float Bs[16][64];       // [k][n]
    __shared__ float red[64][17];      // token partial reduction across tx

    const int tid = threadIdx.x;
    const int tx = tid & 15;           // n dimension
    const int ty = tid >> 4;           // m dimension
    const int m0 = blockIdx.x * 64;

    // load indices
    const int a_row = tid >> 2;        // 0..63
    const int a_kg  = tid & 3;         // 0..3  (k group of 4)
    const int b_row = tid >> 4;        // 0..15 (k)
    const int b_col = (tid & 15) * 4;  // 0..60

    float s_tok[4] = {0.f, 0.f, 0.f, 0.f};

    for (int nc = 0; nc < 8; ++nc) {
        const int nbase = nc * 64;
        float acc[4][4];
        #pragma unroll
        for (int i = 0; i < 4; ++i)
            #pragma unroll
            for (int j = 0; j < 4; ++j) acc[i][j] = 0.f;

        for (int k0 = 0; k0 < DD; k0 += 16) {
            // load X tile (transposed into As)
            float4 xv = *(const float4*)(X + (size_t)(m0 + a_row) * DD + k0 + a_kg * 4);
            As[a_kg * 4 + 0][a_row] = xv.x;
            As[a_kg * 4 + 1][a_row] = xv.y;
            As[a_kg * 4 + 2][a_row] = xv.z;
            As[a_kg * 4 + 3][a_row] = xv.w;
            // load W1 tile
            float4 wv = *(const float4*)(W1 + (size_t)(k0 + b_row) * HH + nbase + b_col);
            *(float4*)&Bs[b_row][b_col] = wv;
            __syncthreads();

            #pragma unroll
            for (int k = 0; k < 16; ++k) {
                float4 av = *(const float4*)&As[k][ty * 4];
                float4 bv = *(const float4*)&Bs[k][tx * 4];
                float a[4] = {av.x, av.y, av.z, av.w};
                float b[4] = {bv.x, bv.y, bv.z, bv.w};
                #pragma unroll
                for (int i = 0; i < 4; ++i)
                    #pragma unroll
                    for (int j = 0; j < 4; ++j)
                        acc[i][j] = fmaf(a[i], b[j], acc[i][j]);
            }
            __syncthreads();
        }

        // epilogue for this n-chunk: relu(acc + b1) * W2, accumulate per token
        #pragma unroll
        for (int j = 0; j < 4; ++j) {
            const int n = nbase + tx * 4 + j;
            const float bb = b1[n];
            const float w2 = W2[n];
            #pragma unroll
            for (int i = 0; i < 4; ++i)
                s_tok[i] += fmaxf(acc[i][j] + bb, 0.f) * w2;
        }
    }

    // reduce s_tok across tx (16 lanes) per token
    #pragma unroll
    for (int i = 0; i < 4; ++i)
        red[ty * 4 + i][tx] = s_tok[i];
    __syncthreads();

    if (tid < 64) {
        float s = 0.f;
        #pragma unroll
        for (int t = 0; t < 16; ++t) s += red[tid][t];
        g_logits[m0 + tid] = s + b2[0];
    }
}

// ---------------------------------------------------------------------------
// K2: per-batch boundary sample + exclusive scan (one block per batch)
// ---------------------------------------------------------------------------
__global__ __launch_bounds__(1024) void scan_kernel(const float* __restrict__ noise_u) {
    const int b = blockIdx.x;
    const int tid = threadIdx.x;
    const int base = b * LL + tid * 4;

    int hd[4];
    #pragma unroll
    for (int j = 0; j < 4; ++j) {
        float u = noise_u[base + j];
        float x = g_logits[base + j] + logf(u) - log1pf(-u);
        hd[j] = (x > 0.f) ? 1 : 0;   // sigmoid(x) > 0.5  <=>  x > 0
    }
    int p = hd[0] + hd[1] + hd[2] + hd[3];

    const int lane = tid & 31;
    const int warp = tid >> 5;
    int v = p;
    #pragma unroll
    for (int off = 1; off < 32; off <<= 1) {
        int n = __shfl_up_sync(0xffffffffu, v, off);
        if (lane >= off) v += n;
    }
    __shared__ int wsum[32];
    if (lane == 31) wsum[warp] = v;
    __syncthreads();
    if (warp == 0) {
        int w = wsum[lane];
        #pragma unroll
        for (int off = 1; off < 32; off <<= 1) {
            int n = __shfl_up_sync(0xffffffffu, w, off);
            if (lane >= off) w += n;
        }
        wsum[lane] = w;
    }
    __syncthreads();

    int excl = (warp ? wsum[warp - 1] : 0) + v - p;   // exclusive prefix before this thread
    int run = excl;
    #pragma unroll
    for (int j = 0; j < 4; ++j) {
        g_seg[base + j] = run;                       // cumsum - hard = exclusive
        g_hard[base + j] = (unsigned char)hd[j];
        run += hd[j];
    }
    if (tid == 1023) g_bcnt[b] = run;                // batch total boundaries
}

// ---------------------------------------------------------------------------
// K3: scalars (loss, num_boundaries, total_positions)
// ---------------------------------------------------------------------------
__global__ void finalize_kernel(float* outs) {
    int nb = 0;
    #pragma unroll
    for (int i = 0; i < BB; ++i) nb += g_bcnt[i];
    float ratio = (float)nb / (float)NTOK;
    float loss = fmaxf(fabsf(ratio - 0.25f) - 0.05f, 0.f);
    outs[0] = loss;
    outs[1] = (float)nb;
    outs[2] = (float)NTOK;
}

// ---------------------------------------------------------------------------
// K4: segment mean pooling — one warp per segment-start token walks its run
// ---------------------------------------------------------------------------
__global__ __launch_bounds__(256) void pool_kernel(
    const float* __restrict__ hidden, float* __restrict__ out)
{
    const int gwarp = (blockIdx.x * blockDim.x + threadIdx.x) >> 5;
    const int lane = threadIdx.x & 31;
    if (gwarp >= NTOK) return;
    const int b = gwarp / LL;
    const int l = gwarp % LL;
    const int t = gwarp;

    const bool is_start = (l == 0) || (g_hard[t - 1] != 0);
    if (!is_start) return;

    float sum[DD / 32];
    #pragma unroll
    for (int i = 0; i < DD / 32; ++i) sum[i] = 0.f;

    int j = l;
    int count = 0;
    while (true) {
        const float* row = hidden + ((size_t)b * LL + j) * DD;
        #pragma unroll
        for (int i = 0; i < DD / 32; ++i) sum[i] += row[lane + 32 * i];
        ++count;
        if (g_hard[b * LL + j] || j == LL - 1) break;
        ++j;
    }

    const int s = g_seg[t];
    const float inv = 1.0f / (float)count;
    float* orow = out + ((size_t)b * LL + s) * DD;
    #pragma unroll
    for (int i = 0; i < DD / 32; ++i) orow[lane + 32 * i] = sum[i] * inv;
}

// ---------------------------------------------------------------------------
extern "C" void kernel_launch(void* const* d_in, const int* in_sizes, int n_in,
                              void* d_out, int out_size) {
    const float* hidden  = (const float*)d_in[0];
    const float* W1      = (const float*)d_in[1];
    const float* b1      = (const float*)d_in[2];
    const float* W2      = (const float*)d_in[3];
    const float* b2      = (const float*)d_in[4];
    const float* noise_u = (const float*)d_in[5];
    float* out = (float*)d_out;

    zero_kernel<<<2048, 256>>>((float4*)out, POOLED_ELEMS / 4);
    gemm_logits_kernel<<<NTOK / 64, 256>>>(hidden, W1, b1, W2, b2);
    scan_kernel<<<BB, 1024>>>(noise_u);
    finalize_kernel<<<1, 1>>>(out + (out_size - 3));
    pool_kernel<<<NTOK / 8, 256>>>(hidden, out);
}

// round 3
// speedup vs baseline: 1.3585x; 1.3585x over previous
#include <cuda_runtime.h>
#include <cuda_bf16.h>
#include <math.h>

// Problem constants (fixed by the dataset)
#define BB 8
#define LL 4096
#define DD 768
#define HH 512
#define NTOK (BB * LL)          // 32768
#define POOLED_ELEMS (BB * LL * DD)

// Device scratch (no allocations allowed)
__device__ float         g_logits[NTOK];
__device__ unsigned char g_hard[NTOK];
__device__ int           g_seg[NTOK];
__device__ int           g_bcnt[BB];

// ---------------------------------------------------------------------------
// K0: zero the pooled region of d_out
// ---------------------------------------------------------------------------
__global__ void zero_kernel(float4* out, int n4) {
    int i = blockIdx.x * blockDim.x + threadIdx.x;
    int stride = gridDim.x * blockDim.x;
    float4 z = make_float4(0.f, 0.f, 0.f, 0.f);
    for (; i < n4; i += stride) out[i] = z;
}

// ---------------------------------------------------------------------------
// K1: fused logits GEMM on tensor cores (3xTF32 split, fp32-equivalent).
// logits[m] = sum_n relu(sum_k X[m,k]*W1[k,n] + b1[n]) * W2[n] + b2
// Block tile: 128 tokens x 128 n-cols, K-chunk 32. 8 warps = 2(m) x 4(n),
// each warp 64 rows x 32 cols = 4x4 m16n8k8 fragments.
// ---------------------------------------------------------------------------
#define MT 128
#define NT 128
#define KT 32
#define AS_STRIDE 36   // bank = (4g+t)%32 -> conflict-free A frag loads
#define BS_STRIDE 136  // bank = (8t+g)%32 -> conflict-free B frag loads

__device__ __forceinline__ unsigned cvt_tf32(float f) {
    unsigned r;
    asm("cvt.rna.tf32.f32 %0, %1;" : "=r"(r) : "f"(f));
    return r;
}

__device__ __forceinline__ void mma_tf32(float* d, unsigned a0, unsigned a1,
                                         unsigned a2, unsigned a3,
                                         unsigned b0, unsigned b1) {
    asm volatile(
        "mma.sync.aligned.m16n8k8.row.col.f32.tf32.tf32.f32 "
        "{%0,%1,%2,%3}, {%4,%5,%6,%7}, {%8,%9}, {%0,%1,%2,%3};"
        : "+f"(d[0]), "+f"(d[1]), "+f"(d[2]), "+f"(d[3])
        : "r"(a0), "r"(a1), "r"(a2), "r"(a3), "r"(b0), "r"(b1));
}

__global__ __launch_bounds__(256) void gemm_logits_tc_kernel(
    const float* __restrict__ X,   // [NTOK, DD]
    const float* __restrict__ W1,  // [DD, HH]
    const float* __restrict__ b1,  // [HH]
    const float* __restrict__ W2,  // [HH]
    const float* __restrict__ b2)  // [1]
{
    __shared__ float As[MT][AS_STRIDE];       // [row][k]
    __shared__ float Bs[KT][BS_STRIDE];       // [k][n]
    __shared__ float red[MT][4];

    const int tid = threadIdx.x;
    const int lane = tid & 31;
    const int wid = tid >> 5;
    const int warp_m = wid & 1;     // 0..1  (64 rows each)
    const int warp_n = wid >> 1;    // 0..3  (32 cols each)
    const int g = lane >> 2;        // groupID
    const int t = lane & 3;         // threadID_in_group
    const int m0 = blockIdx.x * MT;

    // per-row partial logit sums (rows: warp_m*64 + mf*16 + g, +8)
    float s[4][2];
    #pragma unroll
    for (int mf = 0; mf < 4; ++mf) { s[mf][0] = 0.f; s[mf][1] = 0.f; }

    for (int nc = 0; nc < HH / NT; ++nc) {
        const int nbase = nc * NT;

        float acc[4][4][4];
        #pragma unroll
        for (int mf = 0; mf < 4; ++mf)
            #pragma unroll
            for (int nf = 0; nf < 4; ++nf)
                #pragma unroll
                for (int e = 0; e < 4; ++e) acc[mf][nf][e] = 0.f;

        for (int k0 = 0; k0 < DD; k0 += KT) {
            __syncthreads();
            // load X tile: MT x KT (1024 float4, 4 per thread)
            #pragma unroll
            for (int it = 0; it < 4; ++it) {
                int idx = tid + it * 256;
                int row = idx >> 3, c4 = idx & 7;
                float4 v = *(const float4*)(X + (size_t)(m0 + row) * DD + k0 + c4 * 4);
                *(float4*)&As[row][c4 * 4] = v;
            }
            // load W1 tile: KT x NT (1024 float4, 4 per thread)
            #pragma unroll
            for (int it = 0; it < 4; ++it) {
                int idx = tid + it * 256;
                int row = idx >> 5, c4 = idx & 31;
                float4 v = *(const float4*)(W1 + (size_t)(k0 + row) * HH + nbase + c4 * 4);
                *(float4*)&Bs[row][c4 * 4] = v;
            }
            __syncthreads();

            #pragma unroll
            for (int ks = 0; ks < KT / 8; ++ks) {
                const int kb = ks * 8;
                // A fragments: hi/lo split in registers
                unsigned ahi[4][4], alo[4][4];
                #pragma unroll
                for (int mf = 0; mf < 4; ++mf) {
                    const int r = warp_m * 64 + mf * 16 + g;
                    float f0 = As[r][kb + t];
                    float f1 = As[r + 8][kb + t];
                    float f2 = As[r][kb + t + 4];
                    float f3 = As[r + 8][kb + t + 4];
                    ahi[mf][0] = cvt_tf32(f0);
                    ahi[mf][1] = cvt_tf32(f1);
                    ahi[mf][2] = cvt_tf32(f2);
                    ahi[mf][3] = cvt_tf32(f3);
                    alo[mf][0] = cvt_tf32(f0 - __uint_as_float(ahi[mf][0]));
                    alo[mf][1] = cvt_tf32(f1 - __uint_as_float(ahi[mf][1]));
                    alo[mf][2] = cvt_tf32(f2 - __uint_as_float(ahi[mf][2]));
                    alo[mf][3] = cvt_tf32(f3 - __uint_as_float(ahi[mf][3]));
                }
                #pragma unroll
                for (int nf = 0; nf < 4; ++nf) {
                    const int col = warp_n * 32 + nf * 8 + g;
                    float fb0 = Bs[kb + t][col];
                    float fb1 = Bs[kb + t + 4][col];
                    unsigned bhi0 = cvt_tf32(fb0);
                    unsigned bhi1 = cvt_tf32(fb1);
                    unsigned blo0 = cvt_tf32(fb0 - __uint_as_float(bhi0));
                    unsigned blo1 = cvt_tf32(fb1 - __uint_as_float(bhi1));
                    #pragma unroll
                    for (int mf = 0; mf < 4; ++mf) {
                        mma_tf32(acc[mf][nf], ahi[mf][0], ahi[mf][1], ahi[mf][2], ahi[mf][3], bhi0, bhi1);
                        mma_tf32(acc[mf][nf], alo[mf][0], alo[mf][1], alo[mf][2], alo[mf][3], bhi0, bhi1);
                        mma_tf32(acc[mf][nf], ahi[mf][0], ahi[mf][1], ahi[mf][2], ahi[mf][3], blo0, blo1);
                    }
                }
            }
        }

        // epilogue for this n-chunk: relu(acc + b1) * W2 -> per-row partials
        #pragma unroll
        for (int nf = 0; nf < 4; ++nf) {
            const int c0 = nbase + warp_n * 32 + nf * 8 + t * 2;
            const float bb0 = b1[c0],     bb1 = b1[c0 + 1];
            const float w0  = W2[c0],     w1  = W2[c0 + 1];
            #pragma unroll
            for (int mf = 0; mf < 4; ++mf) {
                s[mf][0] += fmaxf(acc[mf][nf][0] + bb0, 0.f) * w0
                          + fmaxf(acc[mf][nf][1] + bb1, 0.f) * w1;
                s[mf][1] += fmaxf(acc[mf][nf][2] + bb0, 0.f) * w0
                          + fmaxf(acc[mf][nf][3] + bb1, 0.f) * w1;
            }
        }
    }

    // reduce across the quad (4 lanes sharing a row)
    #pragma unroll
    for (int mf = 0; mf < 4; ++mf) {
        #pragma unroll
        for (int h = 0; h < 2; ++h) {
            float v = s[mf][h];
            v += __shfl_down_sync(0xffffffffu, v, 1);
            v += __shfl_down_sync(0xffffffffu, v, 2);
            s[mf][h] = v;
        }
    }
    __syncthreads();
    if (t == 0) {
        #pragma unroll
        for (int mf = 0; mf < 4; ++mf) {
            const int r = warp_m * 64 + mf * 16 + g;
            red[r][warp_n] = s[mf][0];
            red[r + 8][warp_n] = s[mf][1];
        }
    }
    __syncthreads();
    if (tid < MT) {
        float v = red[tid][0] + red[tid][1] + red[tid][2] + red[tid][3];
        g_logits[m0 + tid] = v + b2[0];
    }
}

// ---------------------------------------------------------------------------
// K2: per-batch boundary sample + exclusive scan (one block per batch)
// ---------------------------------------------------------------------------
__global__ __launch_bounds__(1024) void scan_kernel(const float* __restrict__ noise_u) {
    const int b = blockIdx.x;
    const int tid = threadIdx.x;
    const int base = b * LL + tid * 4;

    int hd[4];
    #pragma unroll
    for (int j = 0; j < 4; ++j) {
        float u = noise_u[base + j];
        float x = g_logits[base + j] + logf(u) - log1pf(-u);
        hd[j] = (x > 0.f) ? 1 : 0;   // sigmoid(x) > 0.5  <=>  x > 0
    }
    int p = hd[0] + hd[1] + hd[2] + hd[3];

    const int lane = tid & 31;
    const int warp = tid >> 5;
    int v = p;
    #pragma unroll
    for (int off = 1; off < 32; off <<= 1) {
        int n = __shfl_up_sync(0xffffffffu, v, off);
        if (lane >= off) v += n;
    }
    __shared__ int wsum[32];
    if (lane == 31) wsum[warp] = v;
    __syncthreads();
    if (warp == 0) {
        int w = wsum[lane];
        #pragma unroll
        for (int off = 1; off < 32; off <<= 1) {
            int n = __shfl_up_sync(0xffffffffu, w, off);
            if (lane >= off) w += n;
        }
        wsum[lane] = w;
    }
    __syncthreads();

    int excl = (warp ? wsum[warp - 1] : 0) + v - p;   // exclusive prefix before this thread
    int run = excl;
    #pragma unroll
    for (int j = 0; j < 4; ++j) {
        g_seg[base + j] = run;                       // cumsum - hard = exclusive
        g_hard[base + j] = (unsigned char)hd[j];
        run += hd[j];
    }
    if (tid == 1023) g_bcnt[b] = run;                // batch total boundaries
}

// ---------------------------------------------------------------------------
// K3: scalars (loss, num_boundaries, total_positions)
// ---------------------------------------------------------------------------
__global__ void finalize_kernel(float* outs) {
    int nb = 0;
    #pragma unroll
    for (int i = 0; i < BB; ++i) nb += g_bcnt[i];
    float ratio = (float)nb / (float)NTOK;
    float loss = fmaxf(fabsf(ratio - 0.25f) - 0.05f, 0.f);
    outs[0] = loss;
    outs[1] = (float)nb;
    outs[2] = (float)NTOK;
}

// ---------------------------------------------------------------------------
// K4: segment mean pooling — one warp per segment-start token walks its run
// ---------------------------------------------------------------------------
__global__ __launch_bounds__(256) void pool_kernel(
    const float* __restrict__ hidden, float* __restrict__ out)
{
    const int gwarp = (blockIdx.x * blockDim.x + threadIdx.x) >> 5;
    const int lane = threadIdx.x & 31;
    if (gwarp >= NTOK) return;
    const int b = gwarp / LL;
    const int l = gwarp % LL;
    const int t = gwarp;

    const bool is_start = (l == 0) || (g_hard[t - 1] != 0);
    if (!is_start) return;

    float sum[DD / 32];
    #pragma unroll
    for (int i = 0; i < DD / 32; ++i) sum[i] = 0.f;

    int j = l;
    int count = 0;
    while (true) {
        const float* row = hidden + ((size_t)b * LL + j) * DD;
        #pragma unroll
        for (int i = 0; i < DD / 32; ++i) sum[i] += row[lane + 32 * i];
        ++count;
        if (g_hard[b * LL + j] || j == LL - 1) break;
        ++j;
    }

    const int s = g_seg[t];
    const float inv = 1.0f / (float)count;
    float* orow = out + ((size_t)b * LL + s) * DD;
    #pragma unroll
    for (int i = 0; i < DD / 32; ++i) orow[lane + 32 * i] = sum[i] * inv;
}

// ---------------------------------------------------------------------------
extern "C" void kernel_launch(void* const* d_in, const int* in_sizes, int n_in,
                              void* d_out, int out_size) {
    const float* hidden  = (const float*)d_in[0];
    const float* W1      = (const float*)d_in[1];
    const float* b1      = (const float*)d_in[2];
    const float* W2      = (const float*)d_in[3];
    const float* b2      = (const float*)d_in[4];
    const float* noise_u = (const float*)d_in[5];
    float* out = (float*)d_out;

    zero_kernel<<<2048, 256>>>((float4*)out, POOLED_ELEMS / 4);
    gemm_logits_tc_kernel<<<NTOK / MT, 256>>>(hidden, W1, b1, W2, b2);
    scan_kernel<<<BB, 1024>>>(noise_u);
    finalize_kernel<<<1, 1>>>(out + (out_size - 3));
    pool_kernel<<<NTOK / 8, 256>>>(hidden, out);
}

// round 6
// speedup vs baseline: 2.5324x; 1.8641x over previous
#include <cuda_runtime.h>
#include <cuda_bf16.h>
#include <cuda_fp16.h>
#include <math.h>
#include <stdint.h>

// Problem constants (fixed by the dataset)
#define BB 8
#define LL 4096
#define DD 768
#define HH 512
#define NTOK (BB * LL)          // 32768
#define POOLED_ELEMS (BB * LL * DD)

// Arch-specific feature gate: tcgen05/TMEM only exist when this TU is compiled
// through an arch-specific virtual arch (compute_103a/compute_100a).
#if defined(__CUDA_ARCH__) && (defined(__CUDA_ARCH_FEAT_SM103_ALL) || \
    defined(__CUDA_ARCH_FEAT_SM100_ALL) || defined(__CUDA_ARCH_SPECIFIC__) || \
    defined(__CUDA_ARCH_FAMILY_SPECIFIC__))
#define HAS_TC05 1
#else
#define HAS_TC05 0
#endif

// Device scratch (no allocations allowed)
__device__ float         g_logits[NTOK];
__device__ unsigned char g_hard[NTOK];
__device__ int           g_seg[NTOK];
__device__ int           g_bcnt[BB];
// W1 prep (tcgen05 path): K-major planes [HH][DD]
__device__ float         g_w1t_hi[HH * DD];   // tf32(w)
__device__ __half        g_w1t_h16[HH * DD];  // f16(w)
__device__ __half        g_w1t_l16[HH * DD];  // f16(w - tf32(w))

// ---------------------------------------------------------------------------
// Common helpers
// ---------------------------------------------------------------------------
__device__ __forceinline__ unsigned cvt_tf32(float f) {
    unsigned r;
    asm("cvt.rna.tf32.f32 %0, %1;" : "=r"(r) : "f"(f));
    return r;
}
__device__ __forceinline__ uint32_t smem_u32(const void* p) {
    uint32_t a;
    asm("{ .reg .u64 t; cvta.to.shared.u64 t, %1; cvt.u32.u64 %0, t; }" : "=r"(a) : "l"(p));
    return a;
}
__device__ __forceinline__ uint32_t sw128(uint32_t off) {
    return off ^ ((off >> 3) & 0x70);
}

// ---------------------------------------------------------------------------
// K0: zero the pooled region of d_out
// ---------------------------------------------------------------------------
__global__ void zero_kernel(float4* out, int n4) {
    int i = blockIdx.x * blockDim.x + threadIdx.x;
    int stride = gridDim.x * blockDim.x;
    float4 z = make_float4(0.f, 0.f, 0.f, 0.f);
    for (; i < n4; i += stride) out[i] = z;
}

// ---------------------------------------------------------------------------
// K-pre (tcgen05 path only): transpose W1 [DD,HH] -> K-major planes
// ---------------------------------------------------------------------------
__global__ __launch_bounds__(256) void w1prep_kernel(const float* __restrict__ W1) {
#if HAS_TC05
    int idx = blockIdx.x * 256 + threadIdx.x;
    if (idx >= DD * HH) return;
    int k = idx / HH;
    int n = idx % HH;
    float w = W1[idx];
    unsigned hi = cvt_tf32(w);
    float hif = __uint_as_float(hi);
    g_w1t_hi[n * DD + k] = hif;
    g_w1t_h16[n * DD + k] = __float2half_rn(w);
    g_w1t_l16[n * DD + k] = __float2half_rn(w - hif);
#endif
}

// ===========================================================================
// PATH A: tcgen05 GEMM (compiled only in arch-specific passes)
// ===========================================================================
#define KC 32
#define NH 256
#define NUM_CHUNK (DD / KC)      // 24
#define NUM_JOB (2 * NUM_CHUNK)  // 48

#define OFF_TMEMPTR 0
#define OFF_MBAR0   16
#define OFF_MBAR1   24
#define OFF_B1S     64
#define OFF_W2S     (64 + 2048)
#define OFF_STAGE   5120
#define OFF_A_HI    0
#define OFF_A_F16   16384
#define OFF_B_HI    32768
#define OFF_B_F16   65536
#define STAGE_SZ    98304
#define SMEM_TOTAL  (OFF_STAGE + 2 * STAGE_SZ + 1024)

#if HAS_TC05
__device__ __forceinline__ uint32_t elect_one() {
    uint32_t p;
    asm volatile("{\n\t.reg .pred p;\n\telect.sync _|p, 0xFFFFFFFF;\n\tselp.b32 %0, 1, 0, p;\n\t}" : "=r"(p));
    return p;
}
__device__ __forceinline__ uint64_t make_sw128_desc(uint32_t addr) {
    const uint64_t base = (2ull << 61) | (1ull << 46) | (64ull << 32) | (1ull << 16);
    return base | ((uint64_t)(addr >> 4) & 0x3FFF);
}
__device__ __forceinline__ void tc05_mma_ss(uint32_t d_tmem, uint64_t a_desc,
                                            uint64_t b_desc, uint32_t idesc,
                                            uint32_t enable, int kind_tf32) {
    if (kind_tf32) {
        asm volatile(
            "{\n\t.reg .pred p;\n\tsetp.ne.u32 p, %5, 0;\n\t"
            "tcgen05.mma.cta_group::1.kind::tf32 [%0], %1, %2, %3, {%4, %4, %4, %4}, p;\n\t}"
            :: "r"(d_tmem), "l"(a_desc), "l"(b_desc), "r"(idesc), "r"(0u), "r"(enable)
            : "memory");
    } else {
        asm volatile(
            "{\n\t.reg .pred p;\n\tsetp.ne.u32 p, %5, 0;\n\t"
            "tcgen05.mma.cta_group::1.kind::f16 [%0], %1, %2, %3, {%4, %4, %4, %4}, p;\n\t}"
            :: "r"(d_tmem), "l"(a_desc), "l"(b_desc), "r"(idesc), "r"(0u), "r"(enable)
            : "memory");
    }
}
#define MBAR_INIT(addr, cnt) \
    asm volatile("mbarrier.init.shared.b64 [%0], %1;" :: "r"(addr), "r"(cnt) : "memory")
#define TC05_COMMIT(addr) \
    asm volatile("tcgen05.commit.cta_group::1.mbarrier::arrive::one.shared::cluster.b64 [%0];" \
                 :: "r"(addr) : "memory")
#define MBAR_WAIT(addr, ph) do {                                                   \
    uint32_t _m = (addr), _p = (ph), _d;                                           \
    asm volatile("{\n\t.reg .pred p;\n\t"                                          \
        "mbarrier.try_wait.parity.acquire.cta.shared::cta.b64 p, [%1], %2;\n\t"    \
        "selp.b32 %0, 1, 0, p;\n\t}" : "=r"(_d) : "r"(_m), "r"(_p) : "memory");    \
    if (!_d) {                                                                     \
        asm volatile("{\n\t.reg .pred P1;\n\t"                                     \
            "W_%=:\n\t"                                                            \
            "mbarrier.try_wait.parity.acquire.cta.shared::cta.b64 P1, [%0], %1, 0x989680;\n\t" \
            "@P1 bra.uni D_%=;\n\tbra.uni W_%=;\n\tD_%=:\n\t}"                     \
            :: "r"(_m), "r"(_p) : "memory");                                       \
    } } while (0)
#define FENCE_ASYNC() asm volatile("fence.proxy.async.shared::cta;" ::: "memory")
#define TC05_FENCE_AFTER() asm volatile("tcgen05.fence::after_thread_sync;" ::: "memory")
#define TC05_WAIT_LD() asm volatile("tcgen05.wait::ld.sync.aligned;" ::: "memory")
#define TC05_LD_X32(r, a)                                                          \
    asm volatile("tcgen05.ld.sync.aligned.32x32b.x32.b32 "                         \
        "{%0, %1, %2, %3, %4, %5, %6, %7, %8, %9, %10, %11, %12, %13, %14, %15, "  \
        " %16, %17, %18, %19, %20, %21, %22, %23, %24, %25, %26, %27, %28, %29, %30, %31}, [%32];" \
        : "=r"((r)[0]), "=r"((r)[1]), "=r"((r)[2]), "=r"((r)[3]),                  \
          "=r"((r)[4]), "=r"((r)[5]), "=r"((r)[6]), "=r"((r)[7]),                  \
          "=r"((r)[8]), "=r"((r)[9]), "=r"((r)[10]), "=r"((r)[11]),                \
          "=r"((r)[12]), "=r"((r)[13]), "=r"((r)[14]), "=r"((r)[15]),              \
          "=r"((r)[16]), "=r"((r)[17]), "=r"((r)[18]), "=r"((r)[19]),              \
          "=r"((r)[20]), "=r"((r)[21]), "=r"((r)[22]), "=r"((r)[23]),              \
          "=r"((r)[24]), "=r"((r)[25]), "=r"((r)[26]), "=r"((r)[27]),              \
          "=r"((r)[28]), "=r"((r)[29]), "=r"((r)[30]), "=r"((r)[31])               \
        : "r"(a))

#define IDESC_TF32 ((1u << 4) | (2u << 7) | (2u << 10) | ((NH / 8) << 17) | ((128 / 16) << 24))
#define IDESC_F16  ((1u << 4) | (0u << 7) | (0u << 10) | ((NH / 8) << 17) | ((128 / 16) << 24))
#endif // HAS_TC05

__global__ __launch_bounds__(256, 1)
void gemm_logits_tc05_kernel(
    const float* __restrict__ X,   // [NTOK, DD]
    const float* __restrict__ b1,  // [HH]
    const float* __restrict__ W2,  // [HH]
    const float* __restrict__ b2)  // [1]
{
#if HAS_TC05
    extern __shared__ char dsm[];
    const uint32_t smem_raw = smem_u32(dsm);
    const uint32_t sb = (smem_raw + 1023u) & ~1023u;
    char* base = dsm + (sb - smem_raw);
    const int tid = threadIdx.x;
    const int lane = tid & 31;
    const int wid = tid >> 5;
    const int m0 = blockIdx.x * 128;

    if (wid == 0) {
        asm volatile("tcgen05.alloc.cta_group::1.sync.aligned.shared::cta.b32 [%0], %1;"
                     :: "r"(sb + OFF_TMEMPTR), "r"(512u) : "memory");
    }
    if (tid == 0) {
        MBAR_INIT(sb + OFF_MBAR0, 1);
        MBAR_INIT(sb + OFF_MBAR1, 1);
    }
    for (int i = tid; i < HH; i += 256) {
        *(float*)(base + OFF_B1S + i * 4) = b1[i];
        *(float*)(base + OFF_W2S + i * 4) = W2[i];
    }
    __syncthreads();
    uint32_t tmem_base;
    asm volatile("ld.shared.b32 %0, [%1];" : "=r"(tmem_base) : "r"(sb + OFF_TMEMPTR));

    for (int j = 0; j < NUM_JOB; ++j) {
        const int buf = j & 1;
        const int pass = j / NUM_CHUNK;
        const int chunk = j % NUM_CHUNK;
        const int k0 = chunk * KC;
        const int nbase = pass * NH;
        char* stgp = base + OFF_STAGE + buf * STAGE_SZ;
        const uint32_t stg = sb + OFF_STAGE + buf * STAGE_SZ;
        const uint32_t mbar = sb + (buf ? OFF_MBAR1 : OFF_MBAR0);

        if (j >= 2) MBAR_WAIT(mbar, ((j >> 1) - 1) & 1);

        // A tiles: X[m0.., k0..k0+31] -> A_HI (tf32 fp32) + A_F16 ([h(a)|h(alo)])
        #pragma unroll
        for (int it = 0; it < 4; ++it) {
            int idx = tid + it * 256;         // 0..1023
            int r = idx >> 3, c = idx & 7;
            float4 v = *(const float4*)(X + (size_t)(m0 + r) * DD + k0 + c * 4);
            unsigned h0 = cvt_tf32(v.x), h1 = cvt_tf32(v.y),
                     h2 = cvt_tf32(v.z), h3 = cvt_tf32(v.w);
            float4 hv = make_float4(__uint_as_float(h0), __uint_as_float(h1),
                                    __uint_as_float(h2), __uint_as_float(h3));
            *(float4*)(stgp + OFF_A_HI + sw128((uint32_t)(r * 128 + c * 16))) = hv;
            uint32_t so = sw128((uint32_t)(r * 128 + c * 8));
            *(__half2*)(stgp + OFF_A_F16 + so)     = __floats2half2_rn(v.x, v.y);
            *(__half2*)(stgp + OFF_A_F16 + so + 4) = __floats2half2_rn(v.z, v.w);
            uint32_t sl = sw128((uint32_t)(r * 128 + 64 + c * 8));
            *(__half2*)(stgp + OFF_A_F16 + sl)     = __floats2half2_rn(v.x - hv.x, v.y - hv.y);
            *(__half2*)(stgp + OFF_A_F16 + sl + 4) = __floats2half2_rn(v.z - hv.z, v.w - hv.w);
        }
        // B_HI: W1T_hi[nbase+n][k0..k0+31]
        #pragma unroll
        for (int it = 0; it < 8; ++it) {
            int idx = tid + it * 256;         // 0..2047
            int n = idx >> 3, c = idx & 7;
            float4 hv = *(const float4*)(g_w1t_hi + (size_t)(nbase + n) * DD + k0 + c * 4);
            *(float4*)(stgp + OFF_B_HI + sw128((uint32_t)(n * 128 + c * 16))) = hv;
        }
        // B_F16: rows [h(w) x32 | h(wlo) x32]
        #pragma unroll
        for (int it = 0; it < 8; ++it) {
            int idx = tid + it * 256;         // 0..2047
            int n = idx >> 3, c = idx & 7;    // c<4: hi groups, c>=4: lo groups
            const __half* src = (c < 4)
                ? (g_w1t_h16 + (size_t)(nbase + n) * DD + k0 + c * 8)
                : (g_w1t_l16 + (size_t)(nbase + n) * DD + k0 + (c - 4) * 8);
            uint4 v = *(const uint4*)src;
            *(uint4*)(stgp + OFF_B_F16 + sw128((uint32_t)(n * 128 + c * 16))) = v;
        }
        FENCE_ASYNC();
        __syncthreads();

        if (wid == 4) {
            if (elect_one()) {
                uint64_t ah = make_sw128_desc(stg + OFF_A_HI);
                uint64_t bh = make_sw128_desc(stg + OFF_B_HI);
                uint64_t af = make_sw128_desc(stg + OFF_A_F16);
                uint64_t bf = make_sw128_desc(stg + OFF_B_F16);
                uint32_t dt = tmem_base + pass * NH;
                #pragma unroll
                for (int ks = 0; ks < 4; ++ks) {
                    uint32_t en = (chunk == 0 && ks == 0) ? 0u : 1u;
                    tc05_mma_ss(dt, ah + ks * 2, bh + ks * 2, IDESC_TF32, en, 1);
                }
                #pragma unroll
                for (int ks = 0; ks < 2; ++ks) {
                    // h(alo) . h(b)   (A lo half at +4 units, B hi half at +0)
                    tc05_mma_ss(dt, af + 4 + ks * 2, bf + ks * 2, IDESC_F16, 1u, 0);
                    // h(a) . h(blo)
                    tc05_mma_ss(dt, af + ks * 2, bf + 4 + ks * 2, IDESC_F16, 1u, 0);
                }
                TC05_COMMIT(mbar);
            }
        }
    }

    MBAR_WAIT(sb + OFF_MBAR0, 1);
    MBAR_WAIT(sb + OFF_MBAR1, 1);
    TC05_FENCE_AFTER();

    if (wid < 4) {
        const float* b1s = (const float*)(base + OFF_B1S);
        const float* w2s = (const float*)(base + OFF_W2S);
        float s = 0.f;
        #pragma unroll
        for (int cb = 0; cb < 512; cb += 32) {
            uint32_t d[32];
            TC05_LD_X32(d, tmem_base + cb);
            TC05_WAIT_LD();
            #pragma unroll
            for (int c = 0; c < 32; ++c) {
                int n = cb + c;
                s += fmaxf(__uint_as_float(d[c]) + b1s[n], 0.f) * w2s[n];
            }
        }
        g_logits[m0 + wid * 32 + lane] = s + b2[0];
    }
    __syncthreads();
    if (wid == 0) {
        asm volatile("tcgen05.relinquish_alloc_permit.cta_group::1.sync.aligned;");
        asm volatile("tcgen05.dealloc.cta_group::1.sync.aligned.b32 %0, %1;"
                     :: "r"(tmem_base), "r"(512u));
    }
#endif // HAS_TC05
}

// ===========================================================================
// PATH B: mma.sync fallback (round-3 kernel, known good; active when no
// arch-specific pass exists)
// ===========================================================================
#define MT 128
#define NT 128
#define KT 32
#define AS_STRIDE 36
#define BS_STRIDE 136

#if !HAS_TC05
__device__ __forceinline__ void mma_tf32(float* d, unsigned a0, unsigned a1,
                                         unsigned a2, unsigned a3,
                                         unsigned b0, unsigned b1) {
    asm volatile(
        "mma.sync.aligned.m16n8k8.row.col.f32.tf32.tf32.f32 "
        "{%0,%1,%2,%3}, {%4,%5,%6,%7}, {%8,%9}, {%0,%1,%2,%3};"
        : "+f"(d[0]), "+f"(d[1]), "+f"(d[2]), "+f"(d[3])
        : "r"(a0), "r"(a1), "r"(a2), "r"(a3), "r"(b0), "r"(b1));
}
#endif

__global__ __launch_bounds__(256) void gemm_logits_fb_kernel(
    const float* __restrict__ X,   // [NTOK, DD]
    const float* __restrict__ W1,  // [DD, HH]
    const float* __restrict__ b1,  // [HH]
    const float* __restrict__ W2,  // [HH]
    const float* __restrict__ b2)  // [1]
{
#if !HAS_TC05
    __shared__ float As[16][68];   // unused layout kept small; real tiles below
    (void)As;
    __shared__ float Asz[MT / 8][1]; (void)Asz;
    // --- actual tiles ---
    __shared__ float Atile[KT][1]; (void)Atile;
#endif
#if !HAS_TC05
    {
        __shared__ float As2[MT][AS_STRIDE];
        __shared__ float Bs2[KT][BS_STRIDE];
        __shared__ float red[MT][4];

        const int tid = threadIdx.x;
        const int lane = tid & 31;
        const int wid = tid >> 5;
        const int warp_m = wid & 1;
        const int warp_n = wid >> 1;
        const int g = lane >> 2;
        const int t = lane & 3;
        const int m0 = blockIdx.x * MT;

        float s[4][2];
        #pragma unroll
        for (int mf = 0; mf < 4; ++mf) { s[mf][0] = 0.f; s[mf][1] = 0.f; }

        for (int nc = 0; nc < HH / NT; ++nc) {
            const int nbase = nc * NT;

            float acc[4][4][4];
            #pragma unroll
            for (int mf = 0; mf < 4; ++mf)
                #pragma unroll
                for (int nf = 0; nf < 4; ++nf)
                    #pragma unroll
                    for (int e = 0; e < 4; ++e) acc[mf][nf][e] = 0.f;

            for (int k0 = 0; k0 < DD; k0 += KT) {
                __syncthreads();
                #pragma unroll
                for (int it = 0; it < 4; ++it) {
                    int idx = tid + it * 256;
                    int row = idx >> 3, c4 = idx & 7;
                    float4 v = *(const float4*)(X + (size_t)(m0 + row) * DD + k0 + c4 * 4);
                    *(float4*)&As2[row][c4 * 4] = v;
                }
                #pragma unroll
                for (int it = 0; it < 4; ++it) {
                    int idx = tid + it * 256;
                    int row = idx >> 5, c4 = idx & 31;
                    float4 v = *(const float4*)(W1 + (size_t)(k0 + row) * HH + nbase + c4 * 4);
                    *(float4*)&Bs2[row][c4 * 4] = v;
                }
                __syncthreads();

                #pragma unroll
                for (int ks = 0; ks < KT / 8; ++ks) {
                    const int kb = ks * 8;
                    unsigned ahi[4][4], alo[4][4];
                    #pragma unroll
                    for (int mf = 0; mf < 4; ++mf) {
                        const int r = warp_m * 64 + mf * 16 + g;
                        float f0 = As2[r][kb + t];
                        float f1 = As2[r + 8][kb + t];
                        float f2 = As2[r][kb + t + 4];
                        float f3 = As2[r + 8][kb + t + 4];
                        ahi[mf][0] = cvt_tf32(f0);
                        ahi[mf][1] = cvt_tf32(f1);
                        ahi[mf][2] = cvt_tf32(f2);
                        ahi[mf][3] = cvt_tf32(f3);
                        alo[mf][0] = cvt_tf32(f0 - __uint_as_float(ahi[mf][0]));
                        alo[mf][1] = cvt_tf32(f1 - __uint_as_float(ahi[mf][1]));
                        alo[mf][2] = cvt_tf32(f2 - __uint_as_float(ahi[mf][2]));
                        alo[mf][3] = cvt_tf32(f3 - __uint_as_float(ahi[mf][3]));
                    }
                    #pragma unroll
                    for (int nf = 0; nf < 4; ++nf) {
                        const int col = warp_n * 32 + nf * 8 + g;
                        float fb0 = Bs2[kb + t][col];
                        float fb1 = Bs2[kb + t + 4][col];
                        unsigned bhi0 = cvt_tf32(fb0);
                        unsigned bhi1 = cvt_tf32(fb1);
                        unsigned blo0 = cvt_tf32(fb0 - __uint_as_float(bhi0));
                        unsigned blo1 = cvt_tf32(fb1 - __uint_as_float(bhi1));
                        #pragma unroll
                        for (int mf = 0; mf < 4; ++mf) {
                            mma_tf32(acc[mf][nf], ahi[mf][0], ahi[mf][1], ahi[mf][2], ahi[mf][3], bhi0, bhi1);
                            mma_tf32(acc[mf][nf], alo[mf][0], alo[mf][1], alo[mf][2], alo[mf][3], bhi0, bhi1);
                            mma_tf32(acc[mf][nf], ahi[mf][0], ahi[mf][1], ahi[mf][2], ahi[mf][3], blo0, blo1);
                        }
                    }
                }
            }

            #pragma unroll
            for (int nf = 0; nf < 4; ++nf) {
                const int c0 = nbase + warp_n * 32 + nf * 8 + t * 2;
                const float bb0 = b1[c0],     bb1 = b1[c0 + 1];
                const float w0  = W2[c0],     w1  = W2[c0 + 1];
                #pragma unroll
                for (int mf = 0; mf < 4; ++mf) {
                    s[mf][0] += fmaxf(acc[mf][nf][0] + bb0, 0.f) * w0
                              + fmaxf(acc[mf][nf][1] + bb1, 0.f) * w1;
                    s[mf][1] += fmaxf(acc[mf][nf][2] + bb0, 0.f) * w0
                              + fmaxf(acc[mf][nf][3] + bb1, 0.f) * w1;
                }
            }
        }

        #pragma unroll
        for (int mf = 0; mf < 4; ++mf) {
            #pragma unroll
            for (int h = 0; h < 2; ++h) {
                float v = s[mf][h];
                v += __shfl_down_sync(0xffffffffu, v, 1);
                v += __shfl_down_sync(0xffffffffu, v, 2);
                s[mf][h] = v;
            }
        }
        __syncthreads();
        if (t == 0) {
            #pragma unroll
            for (int mf = 0; mf < 4; ++mf) {
                const int r = warp_m * 64 + mf * 16 + g;
                red[r][warp_n] = s[mf][0];
                red[r + 8][warp_n] = s[mf][1];
            }
        }
        __syncthreads();
        if (tid < MT) {
            float v = red[tid][0] + red[tid][1] + red[tid][2] + red[tid][3];
            g_logits[m0 + tid] = v + b2[0];
        }
    }
#endif // !HAS_TC05
}

// ---------------------------------------------------------------------------
// K2: per-batch boundary sample + exclusive scan (one block per batch)
// ---------------------------------------------------------------------------
__global__ __launch_bounds__(1024) void scan_kernel(const float* __restrict__ noise_u) {
    const int b = blockIdx.x;
    const int tid = threadIdx.x;
    const int base = b * LL + tid * 4;

    int hd[4];
    #pragma unroll
    for (int j = 0; j < 4; ++j) {
        float u = noise_u[base + j];
        float x = g_logits[base + j] + logf(u) - log1pf(-u);
        hd[j] = (x > 0.f) ? 1 : 0;
    }
    int p = hd[0] + hd[1] + hd[2] + hd[3];

    const int lane = tid & 31;
    const int warp = tid >> 5;
    int v = p;
    #pragma unroll
    for (int off = 1; off < 32; off <<= 1) {
        int n = __shfl_up_sync(0xffffffffu, v, off);
        if (lane >= off) v += n;
    }
    __shared__ int wsum[32];
    if (lane == 31) wsum[warp] = v;
    __syncthreads();
    if (warp == 0) {
        int w = wsum[lane];
        #pragma unroll
        for (int off = 1; off < 32; off <<= 1) {
            int n = __shfl_up_sync(0xffffffffu, w, off);
            if (lane >= off) w += n;
        }
        wsum[lane] = w;
    }
    __syncthreads();

    int excl = (warp ? wsum[warp - 1] : 0) + v - p;
    int run = excl;
    #pragma unroll
    for (int j = 0; j < 4; ++j) {
        g_seg[base + j] = run;
        g_hard[base + j] = (unsigned char)hd[j];
        run += hd[j];
    }
    if (tid == 1023) g_bcnt[b] = run;
}

// ---------------------------------------------------------------------------
// K3: scalars (loss, num_boundaries, total_positions)
// ---------------------------------------------------------------------------
__global__ void finalize_kernel(float* outs) {
    int nb = 0;
    #pragma unroll
    for (int i = 0; i < BB; ++i) nb += g_bcnt[i];
    float ratio = (float)nb / (float)NTOK;
    float loss = fmaxf(fabsf(ratio - 0.25f) - 0.05f, 0.f);
    outs[0] = loss;
    outs[1] = (float)nb;
    outs[2] = (float)NTOK;
}

// ---------------------------------------------------------------------------
// K4: segment mean pooling — one warp per segment-start token walks its run
// ---------------------------------------------------------------------------
__global__ __launch_bounds__(256) void pool_kernel(
    const float* __restrict__ hidden, float* __restrict__ out)
{
    const int gwarp = (blockIdx.x * blockDim.x + threadIdx.x) >> 5;
    const int lane = threadIdx.x & 31;
    if (gwarp >= NTOK) return;
    const int b = gwarp / LL;
    const int l = gwarp % LL;
    const int t = gwarp;

    const bool is_start = (l == 0) || (g_hard[t - 1] != 0);
    if (!is_start) return;

    float sum[DD / 32];
    #pragma unroll
    for (int i = 0; i < DD / 32; ++i) sum[i] = 0.f;

    int j = l;
    int count = 0;
    while (true) {
        const float* row = hidden + ((size_t)b * LL + j) * DD;
        #pragma unroll
        for (int i = 0; i < DD / 32; ++i) sum[i] += row[lane + 32 * i];
        ++count;
        if (g_hard[b * LL + j] || j == LL - 1) break;
        ++j;
    }

    const int s = g_seg[t];
    const float inv = 1.0f / (float)count;
    float* orow = out + ((size_t)b * LL + s) * DD;
    #pragma unroll
    for (int i = 0; i < DD / 32; ++i) orow[lane + 32 * i] = sum[i] * inv;
}

// ---------------------------------------------------------------------------
extern "C" void kernel_launch(void* const* d_in, const int* in_sizes, int n_in,
                              void* d_out, int out_size) {
    const float* hidden  = (const float*)d_in[0];
    const float* W1      = (const float*)d_in[1];
    const float* b1      = (const float*)d_in[2];
    const float* W2      = (const float*)d_in[3];
    const float* b2      = (const float*)d_in[4];
    const float* noise_u = (const float*)d_in[5];
    float* out = (float*)d_out;

    cudaFuncSetAttribute(gemm_logits_tc05_kernel,
                         cudaFuncAttributeMaxDynamicSharedMemorySize, SMEM_TOTAL);

    zero_kernel<<<2048, 256>>>((float4*)out, POOLED_ELEMS / 4);
    w1prep_kernel<<<(DD * HH) / 256, 256>>>(W1);
    // Exactly one of the two GEMMs has a body in the loaded cubin.
    gemm_logits_tc05_kernel<<<NTOK / 128, 256, SMEM_TOTAL>>>(hidden, b1, W2, b2);
    gemm_logits_fb_kernel<<<NTOK / MT, 256>>>(hidden, W1, b1, W2, b2);
    scan_kernel<<<BB, 1024>>>(noise_u);
    finalize_kernel<<<1, 1>>>(out + (out_size - 3));
    pool_kernel<<<NTOK / 8, 256>>>(hidden, out);
}

// round 8
// speedup vs baseline: 4.4031x; 1.7387x over previous
#include <cuda_runtime.h>
#include <cuda_bf16.h>
#include <cuda_fp16.h>
#include <math.h>
#include <stdint.h>

// Problem constants (fixed by the dataset)
#define BB 8
#define LL 4096
#define DD 768
#define HH 512
#define NTOK (BB * LL)          // 32768
#define POOLED_ELEMS (BB * LL * DD)

// Arch-specific feature gate: tcgen05/TMEM only exist when this TU is compiled
// through an arch-specific virtual arch (compute_103a). Proven live in R6.
#if defined(__CUDA_ARCH__) && (defined(__CUDA_ARCH_FEAT_SM103_ALL) || \
    defined(__CUDA_ARCH_FEAT_SM100_ALL) || defined(__CUDA_ARCH_SPECIFIC__) || \
    defined(__CUDA_ARCH_FAMILY_SPECIFIC__))
#define HAS_TC05 1
#else
#define HAS_TC05 0
#endif

// Device scratch (no allocations allowed)
__device__ float         g_logits[NTOK];
__device__ unsigned char g_hard[NTOK];
__device__ int           g_seg[NTOK];
__device__ int           g_bcnt[BB];
// W1 prep (tcgen05 path): K-major f16 split planes [HH][DD]
__device__ __half        g_w1t_h16[HH * DD];  // f16(w)
__device__ __half        g_w1t_l16[HH * DD];  // f16(w - f16(w))

// ---------------------------------------------------------------------------
// Common helpers
// ---------------------------------------------------------------------------
__device__ __forceinline__ unsigned cvt_tf32(float f) {
    unsigned r;
    asm("cvt.rna.tf32.f32 %0, %1;" : "=r"(r) : "f"(f));
    return r;
}
__device__ __forceinline__ uint32_t smem_u32(const void* p) {
    uint32_t a;
    asm("{ .reg .u64 t; cvta.to.shared.u64 t, %1; cvt.u32.u64 %0, t; }" : "=r"(a) : "l"(p));
    return a;
}
__device__ __forceinline__ uint32_t sw128(uint32_t off) {
    return off ^ ((off >> 3) & 0x70);
}

// ---------------------------------------------------------------------------
// K0: zero the pooled region of d_out
// ---------------------------------------------------------------------------
__global__ void zero_kernel(float4* out, int n4) {
    int i = blockIdx.x * blockDim.x + threadIdx.x;
    int stride = gridDim.x * blockDim.x;
    float4 z = make_float4(0.f, 0.f, 0.f, 0.f);
    for (; i < n4; i += stride) out[i] = z;
}

// ---------------------------------------------------------------------------
// K-pre (tcgen05 path only): transpose W1 [DD,HH] -> K-major f16 hi/lo planes
// ---------------------------------------------------------------------------
__global__ __launch_bounds__(256) void w1prep_kernel(const float* __restrict__ W1) {
#if HAS_TC05
    int idx = blockIdx.x * 256 + threadIdx.x;
    if (idx >= DD * HH) return;
    int k = idx / HH;
    int n = idx % HH;
    float w = W1[idx];
    __half h = __float2half_rn(w);
    g_w1t_h16[n * DD + k] = h;
    g_w1t_l16[n * DD + k] = __float2half_rn(w - __half2float(h));
#endif
}

// ===========================================================================
// PATH A: tcgen05 GEMM, f16x3 split (compiled only in arch-specific passes)
// Per CTA: M=256 (two M=128 tiles sharing B), N=512 via two N=256 passes,
// K-chunk 32. D lives in TMEM: Mtile0 -> cols 0-255, Mtile1 -> cols 256-511.
// Per (pass,chunk): stage A both tiles (f16 hi|lo) + B half (f16 hi|lo),
// issue 12 MMA dispatches; per-pass epilogue drains and accumulates logits.
// ===========================================================================
#define KC 32
#define NUM_CHUNK (DD / KC)      // 24

#define OFF_TMEMPTR 0
#define OFF_MBAR0   16
#define OFF_MBAR1   24
#define OFF_B1S     64
#define OFF_W2S     (64 + 2048)
#define OFF_STAGE   5120
#define OFF_A0      0
#define OFF_A1      16384
#define OFF_Bb      32768
#define STAGE_SZ    65536
#define SMEM_TOTAL  (OFF_STAGE + 2 * STAGE_SZ + 1024)

#if HAS_TC05
__device__ __forceinline__ uint32_t elect_one() {
    uint32_t p;
    asm volatile("{\n\t.reg .pred p;\n\telect.sync _|p, 0xFFFFFFFF;\n\tselp.b32 %0, 1, 0, p;\n\t}" : "=r"(p));
    return p;
}
__device__ __forceinline__ uint64_t make_sw128_desc(uint32_t addr) {
    const uint64_t base = (2ull << 61) | (1ull << 46) | (64ull << 32) | (1ull << 16);
    return base | ((uint64_t)(addr >> 4) & 0x3FFF);
}
__device__ __forceinline__ void tc05_mma_f16_ss(uint32_t d_tmem, uint64_t a_desc,
                                                uint64_t b_desc, uint32_t idesc,
                                                uint32_t enable) {
    asm volatile(
        "{\n\t.reg .pred p;\n\tsetp.ne.u32 p, %5, 0;\n\t"
        "tcgen05.mma.cta_group::1.kind::f16 [%0], %1, %2, %3, {%4, %4, %4, %4}, p;\n\t}"
        :: "r"(d_tmem), "l"(a_desc), "l"(b_desc), "r"(idesc), "r"(0u), "r"(enable)
        : "memory");
}
#define MBAR_INIT(addr, cnt) \
    asm volatile("mbarrier.init.shared.b64 [%0], %1;" :: "r"(addr), "r"(cnt) : "memory")
#define TC05_COMMIT(addr) \
    asm volatile("tcgen05.commit.cta_group::1.mbarrier::arrive::one.shared::cluster.b64 [%0];" \
                 :: "r"(addr) : "memory")
#define MBAR_WAIT(addr, ph) do {                                                   \
    uint32_t _m = (addr), _p = (ph), _d;                                           \
    asm volatile("{\n\t.reg .pred p;\n\t"                                          \
        "mbarrier.try_wait.parity.acquire.cta.shared::cta.b64 p, [%1], %2;\n\t"    \
        "selp.b32 %0, 1, 0, p;\n\t}" : "=r"(_d) : "r"(_m), "r"(_p) : "memory");    \
    if (!_d) {                                                                     \
        asm volatile("{\n\t.reg .pred P1;\n\t"                                     \
            "W_%=:\n\t"                                                            \
            "mbarrier.try_wait.parity.acquire.cta.shared::cta.b64 P1, [%0], %1, 0x989680;\n\t" \
            "@P1 bra.uni D_%=;\n\tbra.uni W_%=;\n\tD_%=:\n\t}"                     \
            :: "r"(_m), "r"(_p) : "memory");                                       \
    } } while (0)
#define FENCE_ASYNC() asm volatile("fence.proxy.async.shared::cta;" ::: "memory")
#define TC05_FENCE_AFTER() asm volatile("tcgen05.fence::after_thread_sync;" ::: "memory")
#define TC05_FENCE_BEFORE() asm volatile("tcgen05.fence::before_thread_sync;" ::: "memory")
#define TC05_WAIT_LD() asm volatile("tcgen05.wait::ld.sync.aligned;" ::: "memory")
#define TC05_LD_X32(r, a)                                                          \
    asm volatile("tcgen05.ld.sync.aligned.32x32b.x32.b32 "                         \
        "{%0, %1, %2, %3, %4, %5, %6, %7, %8, %9, %10, %11, %12, %13, %14, %15, "  \
        " %16, %17, %18, %19, %20, %21, %22, %23, %24, %25, %26, %27, %28, %29, %30, %31}, [%32];" \
        : "=r"((r)[0]), "=r"((r)[1]), "=r"((r)[2]), "=r"((r)[3]),                  \
          "=r"((r)[4]), "=r"((r)[5]), "=r"((r)[6]), "=r"((r)[7]),                  \
          "=r"((r)[8]), "=r"((r)[9]), "=r"((r)[10]), "=r"((r)[11]),                \
          "=r"((r)[12]), "=r"((r)[13]), "=r"((r)[14]), "=r"((r)[15]),              \
          "=r"((r)[16]), "=r"((r)[17]), "=r"((r)[18]), "=r"((r)[19]),              \
          "=r"((r)[20]), "=r"((r)[21]), "=r"((r)[22]), "=r"((r)[23]),              \
          "=r"((r)[24]), "=r"((r)[25]), "=r"((r)[26]), "=r"((r)[27]),              \
          "=r"((r)[28]), "=r"((r)[29]), "=r"((r)[30]), "=r"((r)[31])               \
        : "r"(a))

// idesc: dtype F32, atype/btype F16(0), N=256, M=128
#define IDESC_F16  ((1u << 4) | ((256 / 8) << 17) | ((128 / 16) << 24))
#endif // HAS_TC05

__global__ __launch_bounds__(256, 1)
void gemm_logits_tc05_kernel(
    const float* __restrict__ X,   // [NTOK, DD]
    const float* __restrict__ b1,  // [HH]
    const float* __restrict__ W2,  // [HH]
    const float* __restrict__ b2)  // [1]
{
#if HAS_TC05
    extern __shared__ char dsm[];
    const uint32_t smem_raw = smem_u32(dsm);
    const uint32_t sb = (smem_raw + 1023u) & ~1023u;
    char* base = dsm + (sb - smem_raw);
    const int tid = threadIdx.x;
    const int lane = tid & 31;
    const int wid = tid >> 5;
    const int m0 = blockIdx.x * 256;

    if (wid == 0) {
        asm volatile("tcgen05.alloc.cta_group::1.sync.aligned.shared::cta.b32 [%0], %1;"
                     :: "r"(sb + OFF_TMEMPTR), "r"(512u) : "memory");
    }
    if (tid == 0) {
        MBAR_INIT(sb + OFF_MBAR0, 1);
        MBAR_INIT(sb + OFF_MBAR1, 1);
    }
    for (int i = tid; i < HH; i += 256) {
        *(float*)(base + OFF_B1S + i * 4) = b1[i];
        *(float*)(base + OFF_W2S + i * 4) = W2[i];
    }
    __syncthreads();
    uint32_t tmem_base;
    asm volatile("ld.shared.b32 %0, [%1];" : "=r"(tmem_base) : "r"(sb + OFF_TMEMPTR));

    const int mt = wid >> 2;              // this thread's Mtile for epilogue
    const int row_in = (wid & 3) * 32 + lane;
    float s = 0.f;                        // per-thread logit accumulator

    for (int pass = 0; pass < 2; ++pass) {
        const int nbase = pass * 256;
        for (int chunk = 0; chunk < NUM_CHUNK; ++chunk) {
            const int j = pass * NUM_CHUNK + chunk;
            const int buf = j & 1;
            const int k0 = chunk * KC;
            char* stgp = base + OFF_STAGE + buf * STAGE_SZ;
            const uint32_t stg = sb + OFF_STAGE + buf * STAGE_SZ;
            const uint32_t mbar = sb + (buf ? OFF_MBAR1 : OFF_MBAR0);

            if (j >= 2) MBAR_WAIT(mbar, ((j >> 1) - 1) & 1);

            // ---- stage A: both M tiles, rows [h(a)x32 | h(alo)x32] (128B, SW128)
            #pragma unroll
            for (int it = 0; it < 8; ++it) {
                int idx = tid + it * 256;          // 0..2047
                int tile = idx >> 10;
                int r = (idx >> 3) & 127;
                int c = idx & 7;
                float4 v = *(const float4*)(X + (size_t)(m0 + tile * 128 + r) * DD + k0 + c * 4);
                __half2 h01 = __floats2half2_rn(v.x, v.y);
                __half2 h23 = __floats2half2_rn(v.z, v.w);
                float2 f01 = __half22float2(h01);
                float2 f23 = __half22float2(h23);
                __half2 l01 = __floats2half2_rn(v.x - f01.x, v.y - f01.y);
                __half2 l23 = __floats2half2_rn(v.z - f23.x, v.w - f23.y);
                char* ab = stgp + (tile ? OFF_A1 : OFF_A0);
                uint32_t so = sw128((uint32_t)(r * 128 + c * 8));
                *(__half2*)(ab + so)     = h01;
                *(__half2*)(ab + so + 4) = h23;
                uint32_t sl = sw128((uint32_t)(r * 128 + 64 + c * 8));
                *(__half2*)(ab + sl)     = l01;
                *(__half2*)(ab + sl + 4) = l23;
            }
            // ---- stage B: rows [h(w)x32 | h(wlo)x32] from prepped planes
            #pragma unroll
            for (int it = 0; it < 8; ++it) {
                int idx = tid + it * 256;          // 0..2047
                int n = idx >> 3, c = idx & 7;     // c<4: hi 16B chunks, c>=4: lo
                const __half* src = (c < 4)
                    ? (g_w1t_h16 + (size_t)(nbase + n) * DD + k0 + c * 8)
                    : (g_w1t_l16 + (size_t)(nbase + n) * DD + k0 + (c - 4) * 8);
                uint4 v = *(const uint4*)src;
                *(uint4*)(stgp + OFF_Bb + sw128((uint32_t)(n * 128 + c * 16))) = v;
            }
            FENCE_ASYNC();
            __syncthreads();

            if (wid == 4) {
                if (elect_one()) {
                    uint64_t bd = make_sw128_desc(stg + OFF_Bb);
                    #pragma unroll
                    for (int m = 0; m < 2; ++m) {
                        uint64_t ad = make_sw128_desc(stg + (m ? OFF_A1 : OFF_A0));
                        uint32_t dt = tmem_base + m * 256;
                        #pragma unroll
                        for (int ks = 0; ks < 2; ++ks) {
                            uint32_t en = (chunk == 0 && ks == 0) ? 0u : 1u;
                            // h(a).h(b)
                            tc05_mma_f16_ss(dt, ad + ks * 2, bd + ks * 2, IDESC_F16, en);
                            // h(alo).h(b)
                            tc05_mma_f16_ss(dt, ad + 4 + ks * 2, bd + ks * 2, IDESC_F16, 1u);
                            // h(a).h(blo)
                            tc05_mma_f16_ss(dt, ad + ks * 2, bd + 4 + ks * 2, IDESC_F16, 1u);
                        }
                    }
                    TC05_COMMIT(mbar);
                }
            }
        }

        // ---- drain this pass (last use idx of each buffer has odd parity)
        MBAR_WAIT(sb + OFF_MBAR0, 1);
        MBAR_WAIT(sb + OFF_MBAR1, 1);
        TC05_FENCE_AFTER();

        // ---- per-pass epilogue: all 8 warps read D and accumulate relu+dot
        {
            const float* b1s = (const float*)(base + OFF_B1S);
            const float* w2s = (const float*)(base + OFF_W2S);
            const uint32_t dtb = tmem_base + mt * 256;
            #pragma unroll
            for (int cb = 0; cb < 8; ++cb) {
                uint32_t d[32];
                TC05_LD_X32(d, dtb + cb * 32);
                TC05_WAIT_LD();
                #pragma unroll
                for (int c = 0; c < 32; ++c) {
                    int n = nbase + cb * 32 + c;
                    s += fmaxf(__uint_as_float(d[c]) + b1s[n], 0.f) * w2s[n];
                }
            }
            TC05_FENCE_BEFORE();
            __syncthreads();   // D fully read before next pass overwrites it
        }
    }

    g_logits[m0 + mt * 128 + row_in] = s + b2[0];

    __syncthreads();
    if (wid == 0) {
        asm volatile("tcgen05.relinquish_alloc_permit.cta_group::1.sync.aligned;");
        asm volatile("tcgen05.dealloc.cta_group::1.sync.aligned.b32 %0, %1;"
                     :: "r"(tmem_base), "r"(512u));
    }
#endif // HAS_TC05
}

// ===========================================================================
// PATH B: mma.sync fallback (active only if no arch-specific pass is loaded)
// ===========================================================================
#define MT 128
#define NT 128
#define KT 32
#define AS_STRIDE 36
#define BS_STRIDE 136

#if !HAS_TC05
__device__ __forceinline__ void mma_tf32(float* d, unsigned a0, unsigned a1,
                                         unsigned a2, unsigned a3,
                                         unsigned b0, unsigned b1) {
    asm volatile(
        "mma.sync.aligned.m16n8k8.row.col.f32.tf32.tf32.f32 "
        "{%0,%1,%2,%3}, {%4,%5,%6,%7}, {%8,%9}, {%0,%1,%2,%3};"
        : "+f"(d[0]), "+f"(d[1]), "+f"(d[2]), "+f"(d[3])
        : "r"(a0), "r"(a1), "r"(a2), "r"(a3), "r"(b0), "r"(b1));
}
#endif

__global__ __launch_bounds__(256) void gemm_logits_fb_kernel(
    const float* __restrict__ X,   // [NTOK, DD]
    const float* __restrict__ W1,  // [DD, HH]
    const float* __restrict__ b1,  // [HH]
    const float* __restrict__ W2,  // [HH]
    const float* __restrict__ b2)  // [1]
{
#if !HAS_TC05
    __shared__ float As2[MT][AS_STRIDE];
    __shared__ float Bs2[KT][BS_STRIDE];
    __shared__ float red[MT][4];

    const int tid = threadIdx.x;
    const int lane = tid & 31;
    const int wid = tid >> 5;
    const int warp_m = wid & 1;
    const int warp_n = wid >> 1;
    const int g = lane >> 2;
    const int t = lane & 3;
    const int m0 = blockIdx.x * MT;

    float s[4][2];
    #pragma unroll
    for (int mf = 0; mf < 4; ++mf) { s[mf][0] = 0.f; s[mf][1] = 0.f; }

    for (int nc = 0; nc < HH / NT; ++nc) {
        const int nbase = nc * NT;

        float acc[4][4][4];
        #pragma unroll
        for (int mf = 0; mf < 4; ++mf)
            #pragma unroll
            for (int nf = 0; nf < 4; ++nf)
                #pragma unroll
                for (int e = 0; e < 4; ++e) acc[mf][nf][e] = 0.f;

        for (int k0 = 0; k0 < DD; k0 += KT) {
            __syncthreads();
            #pragma unroll
            for (int it = 0; it < 4; ++it) {
                int idx = tid + it * 256;
                int row = idx >> 3, c4 = idx & 7;
                float4 v = *(const float4*)(X + (size_t)(m0 + row) * DD + k0 + c4 * 4);
                *(float4*)&As2[row][c4 * 4] = v;
            }
            #pragma unroll
            for (int it = 0; it < 4; ++it) {
                int idx = tid + it * 256;
                int row = idx >> 5, c4 = idx & 31;
                float4 v = *(const float4*)(W1 + (size_t)(k0 + row) * HH + nbase + c4 * 4);
                *(float4*)&Bs2[row][c4 * 4] = v;
            }
            __syncthreads();

            #pragma unroll
            for (int ks = 0; ks < KT / 8; ++ks) {
                const int kb = ks * 8;
                unsigned ahi[4][4], alo[4][4];
                #pragma unroll
                for (int mf = 0; mf < 4; ++mf) {
                    const int r = warp_m * 64 + mf * 16 + g;
                    float f0 = As2[r][kb + t];
                    float f1 = As2[r + 8][kb + t];
                    float f2 = As2[r][kb + t + 4];
                    float f3 = As2[r + 8][kb + t + 4];
                    ahi[mf][0] = cvt_tf32(f0);
                    ahi[mf][1] = cvt_tf32(f1);
                    ahi[mf][2] = cvt_tf32(f2);
                    ahi[mf][3] = cvt_tf32(f3);
                    alo[mf][0] = cvt_tf32(f0 - __uint_as_float(ahi[mf][0]));
                    alo[mf][1] = cvt_tf32(f1 - __uint_as_float(ahi[mf][1]));
                    alo[mf][2] = cvt_tf32(f2 - __uint_as_float(ahi[mf][2]));
                    alo[mf][3] = cvt_tf32(f3 - __uint_as_float(ahi[mf][3]));
                }
                #pragma unroll
                for (int nf = 0; nf < 4; ++nf) {
                    const int col = warp_n * 32 + nf * 8 + g;
                    float fb0 = Bs2[kb + t][col];
                    float fb1 = Bs2[kb + t + 4][col];
                    unsigned bhi0 = cvt_tf32(fb0);
                    unsigned bhi1 = cvt_tf32(fb1);
                    unsigned blo0 = cvt_tf32(fb0 - __uint_as_float(bhi0));
                    unsigned blo1 = cvt_tf32(fb1 - __uint_as_float(bhi1));
                    #pragma unroll
                    for (int mf = 0; mf < 4; ++mf) {
                        mma_tf32(acc[mf][nf], ahi[mf][0], ahi[mf][1], ahi[mf][2], ahi[mf][3], bhi0, bhi1);
                        mma_tf32(acc[mf][nf], alo[mf][0], alo[mf][1], alo[mf][2], alo[mf][3], bhi0, bhi1);
                        mma_tf32(acc[mf][nf], ahi[mf][0], ahi[mf][1], ahi[mf][2], ahi[mf][3], blo0, blo1);
                    }
                }
            }
        }

        #pragma unroll
        for (int nf = 0; nf < 4; ++nf) {
            const int c0 = nbase + warp_n * 32 + nf * 8 + t * 2;
            const float bb0 = b1[c0],     bb1 = b1[c0 + 1];
            const float w0  = W2[c0],     w1  = W2[c0 + 1];
            #pragma unroll
            for (int mf = 0; mf < 4; ++mf) {
                s[mf][0] += fmaxf(acc[mf][nf][0] + bb0, 0.f) * w0
                          + fmaxf(acc[mf][nf][1] + bb1, 0.f) * w1;
                s[mf][1] += fmaxf(acc[mf][nf][2] + bb0, 0.f) * w0
                          + fmaxf(acc[mf][nf][3] + bb1, 0.f) * w1;
            }
        }
    }

    #pragma unroll
    for (int mf = 0; mf < 4; ++mf) {
        #pragma unroll
        for (int h = 0; h < 2; ++h) {
            float v = s[mf][h];
            v += __shfl_down_sync(0xffffffffu, v, 1);
            v += __shfl_down_sync(0xffffffffu, v, 2);
            s[mf][h] = v;
        }
    }
    __syncthreads();
    if (t == 0) {
        #pragma unroll
        for (int mf = 0; mf < 4; ++mf) {
            const int r = warp_m * 64 + mf * 16 + g;
            red[r][warp_n] = s[mf][0];
            red[r + 8][warp_n] = s[mf][1];
        }
    }
    __syncthreads();
    if (tid < MT) {
        float v = red[tid][0] + red[tid][1] + red[tid][2] + red[tid][3];
        g_logits[m0 + tid] = v + b2[0];
    }
#endif // !HAS_TC05
}

// ---------------------------------------------------------------------------
// K2: per-batch boundary sample + exclusive scan (one block per batch)
// ---------------------------------------------------------------------------
__global__ __launch_bounds__(1024) void scan_kernel(const float* __restrict__ noise_u) {
    const int b = blockIdx.x;
    const int tid = threadIdx.x;
    const int base = b * LL + tid * 4;

    int hd[4];
    #pragma unroll
    for (int j = 0; j < 4; ++j) {
        float u = noise_u[base + j];
        float x = g_logits[base + j] + logf(u) - log1pf(-u);
        hd[j] = (x > 0.f) ? 1 : 0;
    }
    int p = hd[0] + hd[1] + hd[2] + hd[3];

    const int lane = tid & 31;
    const int warp = tid >> 5;
    int v = p;
    #pragma unroll
    for (int off = 1; off < 32; off <<= 1) {
        int n = __shfl_up_sync(0xffffffffu, v, off);
        if (lane >= off) v += n;
    }
    __shared__ int wsum[32];
    if (lane == 31) wsum[warp] = v;
    __syncthreads();
    if (warp == 0) {
        int w = wsum[lane];
        #pragma unroll
        for (int off = 1; off < 32; off <<= 1) {
            int n = __shfl_up_sync(0xffffffffu, w, off);
            if (lane >= off) w += n;
        }
        wsum[lane] = w;
    }
    __syncthreads();

    int excl = (warp ? wsum[warp - 1] : 0) + v - p;
    int run = excl;
    #pragma unroll
    for (int j = 0; j < 4; ++j) {
        g_seg[base + j] = run;
        g_hard[base + j] = (unsigned char)hd[j];
        run += hd[j];
    }
    if (tid == 1023) g_bcnt[b] = run;
}

// ---------------------------------------------------------------------------
// K3: scalars (loss, num_boundaries, total_positions)
// ---------------------------------------------------------------------------
__global__ void finalize_kernel(float* outs) {
    int nb = 0;
    #pragma unroll
    for (int i = 0; i < BB; ++i) nb += g_bcnt[i];
    float ratio = (float)nb / (float)NTOK;
    float loss = fmaxf(fabsf(ratio - 0.25f) - 0.05f, 0.f);
    outs[0] = loss;
    outs[1] = (float)nb;
    outs[2] = (float)NTOK;
}

// ---------------------------------------------------------------------------
// K4: segment mean pooling — one warp per segment-start token walks its run
// ---------------------------------------------------------------------------
__global__ __launch_bounds__(256) void pool_kernel(
    const float* __restrict__ hidden, float* __restrict__ out)
{
    const int gwarp = (blockIdx.x * blockDim.x + threadIdx.x) >> 5;
    const int lane = threadIdx.x & 31;
    if (gwarp >= NTOK) return;
    const int b = gwarp / LL;
    const int l = gwarp % LL;
    const int t = gwarp;

    const bool is_start = (l == 0) || (g_hard[t - 1] != 0);
    if (!is_start) return;

    float sum[DD / 32];
    #pragma unroll
    for (int i = 0; i < DD / 32; ++i) sum[i] = 0.f;

    int j = l;
    int count = 0;
    while (true) {
        const float* row = hidden + ((size_t)b * LL + j) * DD;
        #pragma unroll
        for (int i = 0; i < DD / 32; ++i) sum[i] += row[lane + 32 * i];
        ++count;
        if (g_hard[b * LL + j] || j == LL - 1) break;
        ++j;
    }

    const int s = g_seg[t];
    const float inv = 1.0f / (float)count;
    float* orow = out + ((size_t)b * LL + s) * DD;
    #pragma unroll
    for (int i = 0; i < DD / 32; ++i) orow[lane + 32 * i] = sum[i] * inv;
}

// ---------------------------------------------------------------------------
extern "C" void kernel_launch(void* const* d_in, const int* in_sizes, int n_in,
                              void* d_out, int out_size) {
    const float* hidden  = (const float*)d_in[0];
    const float* W1      = (const float*)d_in[1];
    const float* b1      = (const float*)d_in[2];
    const float* W2      = (const float*)d_in[3];
    const float* b2      = (const float*)d_in[4];
    const float* noise_u = (const float*)d_in[5];
    float* out = (float*)d_out;

    cudaFuncSetAttribute(gemm_logits_tc05_kernel,
                         cudaFuncAttributeMaxDynamicSharedMemorySize, SMEM_TOTAL);

    zero_kernel<<<2048, 256>>>((float4*)out, POOLED_ELEMS / 4);
    w1prep_kernel<<<(DD * HH) / 256, 256>>>(W1);
    // Exactly one of the two GEMMs has a body in the loaded cubin.
    gemm_logits_tc05_kernel<<<NTOK / 256, 256, SMEM_TOTAL>>>(hidden, b1, W2, b2);
    gemm_logits_fb_kernel<<<NTOK / MT, 256>>>(hidden, W1, b1, W2, b2);
    scan_kernel<<<BB, 1024>>>(noise_u);
    finalize_kernel<<<1, 1>>>(out + (out_size - 3));
    pool_kernel<<<NTOK / 8, 256>>>(hidden, out);
}

// round 10
// speedup vs baseline: 4.8051x; 1.0913x over previous
#include <cuda_runtime.h>
#include <cuda_bf16.h>
#include <cuda_fp16.h>
#include <math.h>
#include <stdint.h>

// Problem constants (fixed by the dataset)
#define BB 8
#define LL 4096
#define DD 768
#define HH 512
#define NTOK (BB * LL)          // 32768
#define POOLED_ELEMS (BB * LL * DD)

// Arch-specific feature gate (proven live on this bench in R6).
#if defined(__CUDA_ARCH__) && (defined(__CUDA_ARCH_FEAT_SM103_ALL) || \
    defined(__CUDA_ARCH_FEAT_SM100_ALL) || defined(__CUDA_ARCH_SPECIFIC__) || \
    defined(__CUDA_ARCH_FAMILY_SPECIFIC__))
#define HAS_TC05 1
#else
#define HAS_TC05 0
#endif

// Device scratch (no allocations allowed)
__device__ float         g_logits[NTOK];
__device__ int           g_segstart[NTOK];   // per batch: start token of segment s
__device__ int           g_nseg[BB];
__device__ int           g_bcnt[BB];
__device__ int           g_done;             // scan completion counter (self-resetting)
// W1 prep (tcgen05 path): K-major f16 split planes [HH][DD]
__device__ __half        g_w1t_h16[HH * DD];  // f16(w)
__device__ __half        g_w1t_l16[HH * DD];  // f16(w - f16(w))

// ---------------------------------------------------------------------------
// Common helpers
// ---------------------------------------------------------------------------
__device__ __forceinline__ unsigned cvt_tf32(float f) {
    unsigned r;
    asm("cvt.rna.tf32.f32 %0, %1;" : "=r"(r) : "f"(f));
    return r;
}
__device__ __forceinline__ uint32_t smem_u32(const void* p) {
    uint32_t a;
    asm("{ .reg .u64 t; cvta.to.shared.u64 t, %1; cvt.u32.u64 %0, t; }" : "=r"(a) : "l"(p));
    return a;
}
__device__ __forceinline__ uint32_t sw128(uint32_t off) {
    return off ^ ((off >> 3) & 0x70);
}

// ---------------------------------------------------------------------------
// K-pre (tcgen05 path only): transpose W1 [DD,HH] -> K-major f16 hi/lo planes
// ---------------------------------------------------------------------------
__global__ __launch_bounds__(256) void w1prep_kernel(const float* __restrict__ W1) {
#if HAS_TC05
    int idx = blockIdx.x * 256 + threadIdx.x;
    if (idx >= DD * HH) return;
    int k = idx / HH;
    int n = idx % HH;
    float w = W1[idx];
    __half h = __float2half_rn(w);
    g_w1t_h16[n * DD + k] = h;
    g_w1t_l16[n * DD + k] = __float2half_rn(w - __half2float(h));
#endif
}

// ===========================================================================
// PATH A: tcgen05 GEMM, f16x3 split. Per CTA: M=256 (2 M-tiles sharing B),
// N=512 via two N=256 passes, K-chunk 32, TRIPLE-buffered staging.
// ===========================================================================
#define KC 32
#define NUM_CHUNK (DD / KC)      // 24
#define NBUF 3

#define OFF_TMEMPTR 0
#define OFF_MBARS   16           // 3 x 8 bytes
#define OFF_B1S     64
#define OFF_W2S     (64 + 2048)
#define OFF_STAGE   5120
#define OFF_A0      0
#define OFF_A1      16384
#define OFF_Bb      32768
#define STAGE_SZ    65536
#define SMEM_TOTAL  (OFF_STAGE + NBUF * STAGE_SZ + 1024)

#if HAS_TC05
__device__ __forceinline__ uint32_t elect_one() {
    uint32_t p;
    asm volatile("{\n\t.reg .pred p;\n\telect.sync _|p, 0xFFFFFFFF;\n\tselp.b32 %0, 1, 0, p;\n\t}" : "=r"(p));
    return p;
}
__device__ __forceinline__ uint64_t make_sw128_desc(uint32_t addr) {
    const uint64_t base = (2ull << 61) | (1ull << 46) | (64ull << 32) | (1ull << 16);
    return base | ((uint64_t)(addr >> 4) & 0x3FFF);
}
__device__ __forceinline__ void tc05_mma_f16_ss(uint32_t d_tmem, uint64_t a_desc,
                                                uint64_t b_desc, uint32_t idesc,
                                                uint32_t enable) {
    asm volatile(
        "{\n\t.reg .pred p;\n\tsetp.ne.u32 p, %5, 0;\n\t"
        "tcgen05.mma.cta_group::1.kind::f16 [%0], %1, %2, %3, {%4, %4, %4, %4}, p;\n\t}"
        :: "r"(d_tmem), "l"(a_desc), "l"(b_desc), "r"(idesc), "r"(0u), "r"(enable)
        : "memory");
}
#define MBAR_INIT(addr, cnt) \
    asm volatile("mbarrier.init.shared.b64 [%0], %1;" :: "r"(addr), "r"(cnt) : "memory")
#define TC05_COMMIT(addr) \
    asm volatile("tcgen05.commit.cta_group::1.mbarrier::arrive::one.shared::cluster.b64 [%0];" \
                 :: "r"(addr) : "memory")
#define MBAR_WAIT(addr, ph) do {                                                   \
    uint32_t _m = (addr), _p = (ph), _d;                                           \
    asm volatile("{\n\t.reg .pred p;\n\t"                                          \
        "mbarrier.try_wait.parity.acquire.cta.shared::cta.b64 p, [%1], %2;\n\t"    \
        "selp.b32 %0, 1, 0, p;\n\t}" : "=r"(_d) : "r"(_m), "r"(_p) : "memory");    \
    if (!_d) {                                                                     \
        asm volatile("{\n\t.reg .pred P1;\n\t"                                     \
            "W_%=:\n\t"                                                            \
            "mbarrier.try_wait.parity.acquire.cta.shared::cta.b64 P1, [%0], %1, 0x989680;\n\t" \
            "@P1 bra.uni D_%=;\n\tbra.uni W_%=;\n\tD_%=:\n\t}"                     \
            :: "r"(_m), "r"(_p) : "memory");                                       \
    } } while (0)
#define FENCE_ASYNC() asm volatile("fence.proxy.async.shared::cta;" ::: "memory")
#define TC05_FENCE_AFTER() asm volatile("tcgen05.fence::after_thread_sync;" ::: "memory")
#define TC05_FENCE_BEFORE() asm volatile("tcgen05.fence::before_thread_sync;" ::: "memory")
#define TC05_WAIT_LD() asm volatile("tcgen05.wait::ld.sync.aligned;" ::: "memory")
#define TC05_LD_X32(r, a)                                                          \
    asm volatile("tcgen05.ld.sync.aligned.32x32b.x32.b32 "                         \
        "{%0, %1, %2, %3, %4, %5, %6, %7, %8, %9, %10, %11, %12, %13, %14, %15, "  \
        " %16, %17, %18, %19, %20, %21, %22, %23, %24, %25, %26, %27, %28, %29, %30, %31}, [%32];" \
        : "=r"((r)[0]), "=r"((r)[1]), "=r"((r)[2]), "=r"((r)[3]),                  \
          "=r"((r)[4]), "=r"((r)[5]), "=r"((r)[6]), "=r"((r)[7]),                  \
          "=r"((r)[8]), "=r"((r)[9]), "=r"((r)[10]), "=r"((r)[11]),                \
          "=r"((r)[12]), "=r"((r)[13]), "=r"((r)[14]), "=r"((r)[15]),              \
          "=r"((r)[16]), "=r"((r)[17]), "=r"((r)[18]), "=r"((r)[19]),              \
          "=r"((r)[20]), "=r"((r)[21]), "=r"((r)[22]), "=r"((r)[23]),              \
          "=r"((r)[24]), "=r"((r)[25]), "=r"((r)[26]), "=r"((r)[27]),              \
          "=r"((r)[28]), "=r"((r)[29]), "=r"((r)[30]), "=r"((r)[31])               \
        : "r"(a))

// idesc: dtype F32, atype/btype F16(0), N=256, M=128
#define IDESC_F16  ((1u << 4) | ((256 / 8) << 17) | ((128 / 16) << 24))
#endif // HAS_TC05

__global__ __launch_bounds__(256, 1)
void gemm_logits_tc05_kernel(
    const float* __restrict__ X,   // [NTOK, DD]
    const float* __restrict__ b1,  // [HH]
    const float* __restrict__ W2,  // [HH]
    const float* __restrict__ b2)  // [1]
{
#if HAS_TC05
    extern __shared__ char dsm[];
    const uint32_t smem_raw = smem_u32(dsm);
    const uint32_t sb = (smem_raw + 1023u) & ~1023u;
    char* base = dsm + (sb - smem_raw);
    const int tid = threadIdx.x;
    const int lane = tid & 31;
    const int wid = tid >> 5;
    const int m0 = blockIdx.x * 256;

    if (wid == 0) {
        asm volatile("tcgen05.alloc.cta_group::1.sync.aligned.shared::cta.b32 [%0], %1;"
                     :: "r"(sb + OFF_TMEMPTR), "r"(512u) : "memory");
    }
    if (tid == 0) {
        #pragma unroll
        for (int k = 0; k < NBUF; ++k) MBAR_INIT(sb + OFF_MBARS + 8 * k, 1);
    }
    for (int i = tid; i < HH; i += 256) {
        *(float*)(base + OFF_B1S + i * 4) = b1[i];
        *(float*)(base + OFF_W2S + i * 4) = W2[i];
    }
    __syncthreads();
    uint32_t tmem_base;
    asm volatile("ld.shared.b32 %0, [%1];" : "=r"(tmem_base) : "r"(sb + OFF_TMEMPTR));

    const int mt = wid >> 2;              // this thread's Mtile for epilogue
    const int row_in = (wid & 3) * 32 + lane;
    float s = 0.f;                        // per-thread logit accumulator

    for (int pass = 0; pass < 2; ++pass) {
        const int nbase = pass * 256;
        for (int chunk = 0; chunk < NUM_CHUNK; ++chunk) {
            const int j = pass * NUM_CHUNK + chunk;
            const int buf = j % NBUF;
            const int u = j / NBUF;            // use index of this buffer
            const int k0 = chunk * KC;
            char* stgp = base + OFF_STAGE + buf * STAGE_SZ;
            const uint32_t stg = sb + OFF_STAGE + buf * STAGE_SZ;
            const uint32_t mbar = sb + OFF_MBARS + 8 * buf;

            // wait until MMAs of this buffer's previous use completed
            if (j >= NBUF) MBAR_WAIT(mbar, (u - 1) & 1);

            // ---- stage A: both M tiles, rows [h(a)x32 | h(alo)x32] (128B, SW128)
            #pragma unroll
            for (int it = 0; it < 8; ++it) {
                int idx = tid + it * 256;          // 0..2047
                int tile = idx >> 10;
                int r = (idx >> 3) & 127;
                int c = idx & 7;
                float4 v = *(const float4*)(X + (size_t)(m0 + tile * 128 + r) * DD + k0 + c * 4);
                __half2 h01 = __floats2half2_rn(v.x, v.y);
                __half2 h23 = __floats2half2_rn(v.z, v.w);
                float2 f01 = __half22float2(h01);
                float2 f23 = __half22float2(h23);
                __half2 l01 = __floats2half2_rn(v.x - f01.x, v.y - f01.y);
                __half2 l23 = __floats2half2_rn(v.z - f23.x, v.w - f23.y);
                char* ab = stgp + (tile ? OFF_A1 : OFF_A0);
                uint32_t so = sw128((uint32_t)(r * 128 + c * 8));
                *(__half2*)(ab + so)     = h01;
                *(__half2*)(ab + so + 4) = h23;
                uint32_t sl = sw128((uint32_t)(r * 128 + 64 + c * 8));
                *(__half2*)(ab + sl)     = l01;
                *(__half2*)(ab + sl + 4) = l23;
            }
            // ---- stage B: rows [h(w)x32 | h(wlo)x32] from prepped planes
            #pragma unroll
            for (int it = 0; it < 8; ++it) {
                int idx = tid + it * 256;          // 0..2047
                int n = idx >> 3, c = idx & 7;     // c<4: hi 16B chunks, c>=4: lo
                const __half* src = (c < 4)
                    ? (g_w1t_h16 + (size_t)(nbase + n) * DD + k0 + c * 8)
                    : (g_w1t_l16 + (size_t)(nbase + n) * DD + k0 + (c - 4) * 8);
                uint4 v = *(const uint4*)src;
                *(uint4*)(stgp + OFF_Bb + sw128((uint32_t)(n * 128 + c * 16))) = v;
            }
            FENCE_ASYNC();
            __syncthreads();

            if (wid == 4) {
                if (elect_one()) {
                    uint64_t bd = make_sw128_desc(stg + OFF_Bb);
                    #pragma unroll
                    for (int m = 0; m < 2; ++m) {
                        uint64_t ad = make_sw128_desc(stg + (m ? OFF_A1 : OFF_A0));
                        uint32_t dt = tmem_base + m * 256;
                        #pragma unroll
                        for (int ks = 0; ks < 2; ++ks) {
                            uint32_t en = (chunk == 0 && ks == 0) ? 0u : 1u;
                            tc05_mma_f16_ss(dt, ad + ks * 2, bd + ks * 2, IDESC_F16, en);
                            tc05_mma_f16_ss(dt, ad + 4 + ks * 2, bd + ks * 2, IDESC_F16, 1u);
                            tc05_mma_f16_ss(dt, ad + ks * 2, bd + 4 + ks * 2, IDESC_F16, 1u);
                        }
                    }
                    TC05_COMMIT(mbar);
                }
            }
        }

        // ---- drain this pass: last NBUF jobs are (pass*24+21..23), each buffer's
        // final use index u = pass*8+7 -> wait parity (u & 1) == 1.
        {
            #pragma unroll
            for (int k = 0; k < NBUF; ++k) MBAR_WAIT(sb + OFF_MBARS + 8 * k, 1);
            TC05_FENCE_AFTER();
        }

        // ---- per-pass epilogue: all 8 warps read D and accumulate relu+dot
        {
            const float* b1s = (const float*)(base + OFF_B1S);
            const float* w2s = (const float*)(base + OFF_W2S);
            const uint32_t dtb = tmem_base + mt * 256;
            #pragma unroll
            for (int cb = 0; cb < 8; ++cb) {
                uint32_t d[32];
                TC05_LD_X32(d, dtb + cb * 32);
                TC05_WAIT_LD();
                #pragma unroll
                for (int c = 0; c < 32; ++c) {
                    int n = nbase + cb * 32 + c;
                    s += fmaxf(__uint_as_float(d[c]) + b1s[n], 0.f) * w2s[n];
                }
            }
            TC05_FENCE_BEFORE();
            __syncthreads();   // D fully read before next pass overwrites it
        }
    }

    g_logits[m0 + mt * 128 + row_in] = s + b2[0];

    __syncthreads();
    if (wid == 0) {
        asm volatile("tcgen05.relinquish_alloc_permit.cta_group::1.sync.aligned;");
        asm volatile("tcgen05.dealloc.cta_group::1.sync.aligned.b32 %0, %1;"
                     :: "r"(tmem_base), "r"(512u));
    }
#endif // HAS_TC05
}

// ===========================================================================
// PATH B: mma.sync fallback (launched only if the tc05 kernel is a stub)
// ===========================================================================
#define MT 128
#define NT 128
#define KT 32
#define AS_STRIDE 36
#define BS_STRIDE 136

#if !HAS_TC05
__device__ __forceinline__ void mma_tf32(float* d, unsigned a0, unsigned a1,
                                         unsigned a2, unsigned a3,
                                         unsigned b0, unsigned b1) {
    asm volatile(
        "mma.sync.aligned.m16n8k8.row.col.f32.tf32.tf32.f32 "
        "{%0,%1,%2,%3}, {%4,%5,%6,%7}, {%8,%9}, {%0,%1,%2,%3};"
        : "+f"(d[0]), "+f"(d[1]), "+f"(d[2]), "+f"(d[3])
        : "r"(a0), "r"(a1), "r"(a2), "r"(a3), "r"(b0), "r"(b1));
}
#endif

__global__ __launch_bounds__(256) void gemm_logits_fb_kernel(
    const float* __restrict__ X,   // [NTOK, DD]
    const float* __restrict__ W1,  // [DD, HH]
    const float* __restrict__ b1,  // [HH]
    const float* __restrict__ W2,  // [HH]
    const float* __restrict__ b2)  // [1]
{
#if !HAS_TC05
    __shared__ float As2[MT][AS_STRIDE];
    __shared__ float Bs2[KT][BS_STRIDE];
    __shared__ float red[MT][4];

    const int tid = threadIdx.x;
    const int lane = tid & 31;
    const int wid = tid >> 5;
    const int warp_m = wid & 1;
    const int warp_n = wid >> 1;
    const int g = lane >> 2;
    const int t = lane & 3;
    const int m0 = blockIdx.x * MT;

    float s[4][2];
    #pragma unroll
    for (int mf = 0; mf < 4; ++mf) { s[mf][0] = 0.f; s[mf][1] = 0.f; }

    for (int nc = 0; nc < HH / NT; ++nc) {
        const int nbase = nc * NT;

        float acc[4][4][4];
        #pragma unroll
        for (int mf = 0; mf < 4; ++mf)
            #pragma unroll
            for (int nf = 0; nf < 4; ++nf)
                #pragma unroll
                for (int e = 0; e < 4; ++e) acc[mf][nf][e] = 0.f;

        for (int k0 = 0; k0 < DD; k0 += KT) {
            __syncthreads();
            #pragma unroll
            for (int it = 0; it < 4; ++it) {
                int idx = tid + it * 256;
                int row = idx >> 3, c4 = idx & 7;
                float4 v = *(const float4*)(X + (size_t)(m0 + row) * DD + k0 + c4 * 4);
                *(float4*)&As2[row][c4 * 4] = v;
            }
            #pragma unroll
            for (int it = 0; it < 4; ++it) {
                int idx = tid + it * 256;
                int row = idx >> 5, c4 = idx & 31;
                float4 v = *(const float4*)(W1 + (size_t)(k0 + row) * HH + nbase + c4 * 4);
                *(float4*)&Bs2[row][c4 * 4] = v;
            }
            __syncthreads();

            #pragma unroll
            for (int ks = 0; ks < KT / 8; ++ks) {
                const int kb = ks * 8;
                unsigned ahi[4][4], alo[4][4];
                #pragma unroll
                for (int mf = 0; mf < 4; ++mf) {
                    const int r = warp_m * 64 + mf * 16 + g;
                    float f0 = As2[r][kb + t];
                    float f1 = As2[r + 8][kb + t];
                    float f2 = As2[r][kb + t + 4];
                    float f3 = As2[r + 8][kb + t + 4];
                    ahi[mf][0] = cvt_tf32(f0);
                    ahi[mf][1] = cvt_tf32(f1);
                    ahi[mf][2] = cvt_tf32(f2);
                    ahi[mf][3] = cvt_tf32(f3);
                    alo[mf][0] = cvt_tf32(f0 - __uint_as_float(ahi[mf][0]));
                    alo[mf][1] = cvt_tf32(f1 - __uint_as_float(ahi[mf][1]));
                    alo[mf][2] = cvt_tf32(f2 - __uint_as_float(ahi[mf][2]));
                    alo[mf][3] = cvt_tf32(f3 - __uint_as_float(ahi[mf][3]));
                }
                #pragma unroll
                for (int nf = 0; nf < 4; ++nf) {
                    const int col = warp_n * 32 + nf * 8 + g;
                    float fb0 = Bs2[kb + t][col];
                    float fb1 = Bs2[kb + t + 4][col];
                    unsigned bhi0 = cvt_tf32(fb0);
                    unsigned bhi1 = cvt_tf32(fb1);
                    unsigned blo0 = cvt_tf32(fb0 - __uint_as_float(bhi0));
                    unsigned blo1 = cvt_tf32(fb1 - __uint_as_float(bhi1));
                    #pragma unroll
                    for (int mf = 0; mf < 4; ++mf) {
                        mma_tf32(acc[mf][nf], ahi[mf][0], ahi[mf][1], ahi[mf][2], ahi[mf][3], bhi0, bhi1);
                        mma_tf32(acc[mf][nf], alo[mf][0], alo[mf][1], alo[mf][2], alo[mf][3], bhi0, bhi1);
                        mma_tf32(acc[mf][nf], ahi[mf][0], ahi[mf][1], ahi[mf][2], ahi[mf][3], blo0, blo1);
                    }
                }
            }
        }

        #pragma unroll
        for (int nf = 0; nf < 4; ++nf) {
            const int c0 = nbase + warp_n * 32 + nf * 8 + t * 2;
            const float bb0 = b1[c0],     bb1 = b1[c0 + 1];
            const float w0  = W2[c0],     w1  = W2[c0 + 1];
            #pragma unroll
            for (int mf = 0; mf < 4; ++mf) {
                s[mf][0] += fmaxf(acc[mf][nf][0] + bb0, 0.f) * w0
                          + fmaxf(acc[mf][nf][1] + bb1, 0.f) * w1;
                s[mf][1] += fmaxf(acc[mf][nf][2] + bb0, 0.f) * w0
                          + fmaxf(acc[mf][nf][3] + bb1, 0.f) * w1;
            }
        }
    }

    #pragma unroll
    for (int mf = 0; mf < 4; ++mf) {
        #pragma unroll
        for (int h = 0; h < 2; ++h) {
            float v = s[mf][h];
            v += __shfl_down_sync(0xffffffffu, v, 1);
            v += __shfl_down_sync(0xffffffffu, v, 2);
            s[mf][h] = v;
        }
    }
    __syncthreads();
    if (t == 0) {
        #pragma unroll
        for (int mf = 0; mf < 4; ++mf) {
            const int r = warp_m * 64 + mf * 16 + g;
            red[r][warp_n] = s[mf][0];
            red[r + 8][warp_n] = s[mf][1];
        }
    }
    __syncthreads();
    if (tid < MT) {
        float v = red[tid][0] + red[tid][1] + red[tid][2] + red[tid][3];
        g_logits[m0 + tid] = v + b2[0];
    }
#endif // !HAS_TC05
}

// ---------------------------------------------------------------------------
// K2: per-batch boundary sample + scan + segment starts + fused scalars.
// One block per batch; last-finishing block computes loss/num_boundaries.
// ---------------------------------------------------------------------------
__global__ __launch_bounds__(1024) void scan_kernel(
    const float* __restrict__ noise_u, float* __restrict__ outs)
{
    const int b = blockIdx.x;
    const int tid = threadIdx.x;
    const int l0 = tid * 4;
    const int base = b * LL + l0;

    int hd[4];
    #pragma unroll
    for (int j = 0; j < 4; ++j) {
        float u = noise_u[base + j];
        float x = g_logits[base + j] + logf(u) - log1pf(-u);
        hd[j] = (x > 0.f) ? 1 : 0;
    }
    int p = hd[0] + hd[1] + hd[2] + hd[3];

    const int lane = tid & 31;
    const int warp = tid >> 5;
    int v = p;
    #pragma unroll
    for (int off = 1; off < 32; off <<= 1) {
        int n = __shfl_up_sync(0xffffffffu, v, off);
        if (lane >= off) v += n;
    }
    __shared__ int wsum[32];
    if (lane == 31) wsum[warp] = v;
    __syncthreads();
    if (warp == 0) {
        int w = wsum[lane];
        #pragma unroll
        for (int off = 1; off < 32; off <<= 1) {
            int n = __shfl_up_sync(0xffffffffu, w, off);
            if (lane >= off) w += n;
        }
        wsum[lane] = w;
    }
    __syncthreads();

    int excl = (warp ? wsum[warp - 1] : 0) + v - p;   // boundaries strictly before l0
    int run = excl;                                    // = seg id of current token
    if (tid == 0) g_segstart[b * LL] = 0;              // segment 0 starts at token 0
    #pragma unroll
    for (int j = 0; j < 4; ++j) {
        if (hd[j]) {
            int nxt = l0 + j + 1;                      // next token starts segment run+1
            if (nxt < LL) g_segstart[b * LL + run + 1] = nxt;
        }
        run += hd[j];
    }
    if (tid == 1023) {
        g_bcnt[b] = run;                               // total boundaries in batch
        g_nseg[b] = run - hd[3] + 1;                   // seg[last] + 1
        __threadfence();
        int done = atomicAdd(&g_done, 1);
        if (done == BB - 1) {
            int nb = 0;
            #pragma unroll
            for (int i = 0; i < BB; ++i) nb += g_bcnt[i];
            float ratio = (float)nb / (float)NTOK;
            outs[0] = fmaxf(fabsf(ratio - 0.25f) - 0.05f, 0.f);
            outs[1] = (float)nb;
            outs[2] = (float)NTOK;
            atomicExch(&g_done, 0);                    // reset for next graph replay
        }
    }
}

// ---------------------------------------------------------------------------
// K4: pooled output — one warp per OUTPUT row (b, s). Covers all rows:
// s < nseg -> segment mean; s >= nseg -> zeros (replaces zero_kernel).
// Known loop bounds (no pointer chasing), float4 loads/stores.
// ---------------------------------------------------------------------------
__global__ __launch_bounds__(256) void pool_kernel(
    const float* __restrict__ hidden, float* __restrict__ out)
{
    const int gwarp = (blockIdx.x * blockDim.x + threadIdx.x) >> 5;
    const int lane = threadIdx.x & 31;
    const int b = gwarp >> 12;          // / LL
    const int s = gwarp & (LL - 1);     // % LL

    float4 acc[6];
    #pragma unroll
    for (int i = 0; i < 6; ++i) acc[i] = make_float4(0.f, 0.f, 0.f, 0.f);

    const int nseg = g_nseg[b];
    if (s < nseg) {
        const int start = g_segstart[b * LL + s];
        const int end = (s + 1 < nseg) ? g_segstart[b * LL + s + 1] : LL;
        const float4* row = (const float4*)(hidden + ((size_t)b * LL + start) * DD);
        for (int j = start; j < end; ++j, row += DD / 4) {
            #pragma unroll
            for (int i = 0; i < 6; ++i) {
                float4 r = row[lane + 32 * i];
                acc[i].x += r.x; acc[i].y += r.y; acc[i].z += r.z; acc[i].w += r.w;
            }
        }
        const float inv = 1.0f / (float)(end - start);
        #pragma unroll
        for (int i = 0; i < 6; ++i) {
            acc[i].x *= inv; acc[i].y *= inv; acc[i].z *= inv; acc[i].w *= inv;
        }
    }

    float4* orow = (float4*)(out + ((size_t)b * LL + s) * DD);
    #pragma unroll
    for (int i = 0; i < 6; ++i) orow[lane + 32 * i] = acc[i];
}

// ---------------------------------------------------------------------------
extern "C" void kernel_launch(void* const* d_in, const int* in_sizes, int n_in,
                              void* d_out, int out_size) {
    const float* hidden  = (const float*)d_in[0];
    const float* W1      = (const float*)d_in[1];
    const float* b1      = (const float*)d_in[2];
    const float* W2      = (const float*)d_in[3];
    const float* b2      = (const float*)d_in[4];
    const float* noise_u = (const float*)d_in[5];
    float* out = (float*)d_out;

    // Which GEMM has a body in the loaded cubin? (host code runs at capture time)
    cudaFuncAttributes attr;
    cudaFuncGetAttributes(&attr, gemm_logits_tc05_kernel);
    const bool tc05_live = attr.numRegs > 24;

    if (tc05_live) {
        cudaFuncSetAttribute(gemm_logits_tc05_kernel,
                             cudaFuncAttributeMaxDynamicSharedMemorySize, SMEM_TOTAL);
        w1prep_kernel<<<(DD * HH) / 256, 256>>>(W1);
        gemm_logits_tc05_kernel<<<NTOK / 256, 256, SMEM_TOTAL>>>(hidden, b1, W2, b2);
    } else {
        gemm_logits_fb_kernel<<<NTOK / MT, 256>>>(hidden, W1, b1, W2, b2);
    }
    scan_kernel<<<BB, 1024>>>(noise_u, out + (out_size - 3));
    pool_kernel<<<NTOK / 8, 256>>>(hidden, out);
}

// round 13
// speedup vs baseline: 5.4471x; 1.1336x over previous
#include <cuda_runtime.h>
#include <cuda_bf16.h>
#include <cuda_fp16.h>
#include <math.h>
#include <stdint.h>

// Problem constants (fixed by the dataset)
#define BB 8
#define LL 4096
#define DD 768
#define HH 512
#define NTOK (BB * LL)          // 32768
#define POOLED_ELEMS (BB * LL * DD)

// Arch-specific feature gate (proven live on this bench in R6).
#if defined(__CUDA_ARCH__) && (defined(__CUDA_ARCH_FEAT_SM103_ALL) || \
    defined(__CUDA_ARCH_FEAT_SM100_ALL) || defined(__CUDA_ARCH_SPECIFIC__) || \
    defined(__CUDA_ARCH_FAMILY_SPECIFIC__))
#define HAS_TC05 1
#else
#define HAS_TC05 0
#endif

// Device scratch (no allocations allowed)
__device__ float         g_logits[NTOK];
__device__ int           g_segstart[NTOK];   // per batch: start token of segment s
__device__ int           g_nseg[BB];
__device__ int           g_bcnt[BB];
__device__ int           g_done;             // scan completion counter (self-resetting)
// W1 prep (tcgen05 path): K-major f16 split planes [HH][DD]
__device__ __half        g_w1t_h16[HH * DD];  // f16(w)
__device__ __half        g_w1t_l16[HH * DD];  // f16(w - f16(w))

// ---------------------------------------------------------------------------
// Common helpers
// ---------------------------------------------------------------------------
__device__ __forceinline__ unsigned cvt_tf32(float f) {
    unsigned r;
    asm("cvt.rna.tf32.f32 %0, %1;" : "=r"(r) : "f"(f));
    return r;
}
__device__ __forceinline__ uint32_t smem_u32(const void* p) {
    uint32_t a;
    asm("{ .reg .u64 t; cvta.to.shared.u64 t, %1; cvt.u32.u64 %0, t; }" : "=r"(a) : "l"(p));
    return a;
}
__device__ __forceinline__ uint32_t sw128(uint32_t off) {
    return off ^ ((off >> 3) & 0x70);
}

// ---------------------------------------------------------------------------
// K-pre (tcgen05 path only): transpose W1 [DD,HH] -> K-major f16 hi/lo planes
// ---------------------------------------------------------------------------
__global__ __launch_bounds__(256) void w1prep_kernel(const float* __restrict__ W1) {
#if HAS_TC05
    int idx = blockIdx.x * 256 + threadIdx.x;
    if (idx >= DD * HH) return;
    int k = idx / HH;
    int n = idx % HH;
    float w = W1[idx];
    __half h = __float2half_rn(w);
    g_w1t_h16[n * DD + k] = h;
    g_w1t_l16[n * DD + k] = __float2half_rn(w - __half2float(h));
#endif
}

// ===========================================================================
// PATH A: tcgen05 GEMM, f16x3 split. Per CTA: M=128, N=512 in a SINGLE
// K-sweep (TMEM: nh0 -> cols 0-255, nh1 -> cols 256-511), K-chunk 32,
// double-buffered staging (A 16KB + B 64KB per chunk). One epilogue.
// ===========================================================================
#define KC 32
#define NUM_CHUNK (DD / KC)      // 24
#define NBUF 2

#define OFF_TMEMPTR 0
#define OFF_MBARS   16           // 2 x 8 bytes
#define OFF_B1S     64
#define OFF_W2S     (64 + 2048)
#define OFF_RED     4224         // 128 rows x 2 halves x 4B
#define OFF_STAGE   6144
#define OFF_A       0
#define OFF_B       16384        // two 32KB n-half blocks
#define STAGE_SZ    81920
#define SMEM_TOTAL  (OFF_STAGE + NBUF * STAGE_SZ + 1024)

#if HAS_TC05
__device__ __forceinline__ uint32_t elect_one() {
    uint32_t p;
    asm volatile("{\n\t.reg .pred p;\n\telect.sync _|p, 0xFFFFFFFF;\n\tselp.b32 %0, 1, 0, p;\n\t}" : "=r"(p));
    return p;
}
__device__ __forceinline__ uint64_t make_sw128_desc(uint32_t addr) {
    const uint64_t base = (2ull << 61) | (1ull << 46) | (64ull << 32) | (1ull << 16);
    return base | ((uint64_t)(addr >> 4) & 0x3FFF);
}
__device__ __forceinline__ void tc05_mma_f16_ss(uint32_t d_tmem, uint64_t a_desc,
                                                uint64_t b_desc, uint32_t idesc,
                                                uint32_t enable) {
    asm volatile(
        "{\n\t.reg .pred p;\n\tsetp.ne.u32 p, %5, 0;\n\t"
        "tcgen05.mma.cta_group::1.kind::f16 [%0], %1, %2, %3, {%4, %4, %4, %4}, p;\n\t}"
        :: "r"(d_tmem), "l"(a_desc), "l"(b_desc), "r"(idesc), "r"(0u), "r"(enable)
        : "memory");
}
#define MBAR_INIT(addr, cnt) \
    asm volatile("mbarrier.init.shared.b64 [%0], %1;" :: "r"(addr), "r"(cnt) : "memory")
#define TC05_COMMIT(addr) \
    asm volatile("tcgen05.commit.cta_group::1.mbarrier::arrive::one.shared::cluster.b64 [%0];" \
                 :: "r"(addr) : "memory")
#define MBAR_WAIT(addr, ph) do {                                                   \
    uint32_t _m = (addr), _p = (ph), _d;                                           \
    asm volatile("{\n\t.reg .pred p;\n\t"                                          \
        "mbarrier.try_wait.parity.acquire.cta.shared::cta.b64 p, [%1], %2;\n\t"    \
        "selp.b32 %0, 1, 0, p;\n\t}" : "=r"(_d) : "r"(_m), "r"(_p) : "memory");    \
    if (!_d) {                                                                     \
        asm volatile("{\n\t.reg .pred P1;\n\t"                                     \
            "W_%=:\n\t"                                                            \
            "mbarrier.try_wait.parity.acquire.cta.shared::cta.b64 P1, [%0], %1, 0x989680;\n\t" \
            "@P1 bra.uni D_%=;\n\tbra.uni W_%=;\n\tD_%=:\n\t}"                     \
            :: "r"(_m), "r"(_p) : "memory");                                       \
    } } while (0)
#define FENCE_ASYNC() asm volatile("fence.proxy.async.shared::cta;" ::: "memory")
#define TC05_FENCE_AFTER() asm volatile("tcgen05.fence::after_thread_sync;" ::: "memory")
#define TC05_FENCE_BEFORE() asm volatile("tcgen05.fence::before_thread_sync;" ::: "memory")
#define TC05_WAIT_LD() asm volatile("tcgen05.wait::ld.sync.aligned;" ::: "memory")
#define TC05_LD_X32(r, a)                                                          \
    asm volatile("tcgen05.ld.sync.aligned.32x32b.x32.b32 "                         \
        "{%0, %1, %2, %3, %4, %5, %6, %7, %8, %9, %10, %11, %12, %13, %14, %15, "  \
        " %16, %17, %18, %19, %20, %21, %22, %23, %24, %25, %26, %27, %28, %29, %30, %31}, [%32];" \
        : "=r"((r)[0]), "=r"((r)[1]), "=r"((r)[2]), "=r"((r)[3]),                  \
          "=r"((r)[4]), "=r"((r)[5]), "=r"((r)[6]), "=r"((r)[7]),                  \
          "=r"((r)[8]), "=r"((r)[9]), "=r"((r)[10]), "=r"((r)[11]),                \
          "=r"((r)[12]), "=r"((r)[13]), "=r"((r)[14]), "=r"((r)[15]),              \
          "=r"((r)[16]), "=r"((r)[17]), "=r"((r)[18]), "=r"((r)[19]),              \
          "=r"((r)[20]), "=r"((r)[21]), "=r"((r)[22]), "=r"((r)[23]),              \
          "=r"((r)[24]), "=r"((r)[25]), "=r"((r)[26]), "=r"((r)[27]),              \
          "=r"((r)[28]), "=r"((r)[29]), "=r"((r)[30]), "=r"((r)[31])               \
        : "r"(a))

// idesc: dtype F32, atype/btype F16(0), N=256, M=128
#define IDESC_F16  ((1u << 4) | ((256 / 8) << 17) | ((128 / 16) << 24))
#endif // HAS_TC05

__global__ __launch_bounds__(256, 1)
void gemm_logits_tc05_kernel(
    const float* __restrict__ X,   // [NTOK, DD]
    const float* __restrict__ b1,  // [HH]
    const float* __restrict__ W2,  // [HH]
    const float* __restrict__ b2)  // [1]
{
#if HAS_TC05
    extern __shared__ char dsm[];
    const uint32_t smem_raw = smem_u32(dsm);
    const uint32_t sb = (smem_raw + 1023u) & ~1023u;
    char* base = dsm + (sb - smem_raw);
    const int tid = threadIdx.x;
    const int lane = tid & 31;
    const int wid = tid >> 5;
    const int m0 = blockIdx.x * 128;

    if (wid == 0) {
        asm volatile("tcgen05.alloc.cta_group::1.sync.aligned.shared::cta.b32 [%0], %1;"
                     :: "r"(sb + OFF_TMEMPTR), "r"(512u) : "memory");
    }
    if (tid == 0) {
        #pragma unroll
        for (int k = 0; k < NBUF; ++k) MBAR_INIT(sb + OFF_MBARS + 8 * k, 1);
    }
    for (int i = tid; i < HH; i += 256) {
        *(float*)(base + OFF_B1S + i * 4) = b1[i];
        *(float*)(base + OFF_W2S + i * 4) = W2[i];
    }
    __syncthreads();
    uint32_t tmem_base;
    asm volatile("ld.shared.b32 %0, [%1];" : "=r"(tmem_base) : "r"(sb + OFF_TMEMPTR));

    for (int chunk = 0; chunk < NUM_CHUNK; ++chunk) {
        const int buf = chunk & 1;
        const int u = chunk >> 1;              // use index of this buffer
        const int k0 = chunk * KC;
        char* stgp = base + OFF_STAGE + buf * STAGE_SZ;
        const uint32_t stg = sb + OFF_STAGE + buf * STAGE_SZ;
        const uint32_t mbar = sb + OFF_MBARS + 8 * buf;

        // wait until MMAs of this buffer's previous use completed
        if (chunk >= NBUF) MBAR_WAIT(mbar, (u - 1) & 1);

        // ---- stage A: one M tile, rows [h(a)x32 | h(alo)x32] (128B, SW128)
        #pragma unroll
        for (int it = 0; it < 4; ++it) {
            int idx = tid + it * 256;          // 0..1023
            int r = idx >> 3;
            int c = idx & 7;
            float4 v = *(const float4*)(X + (size_t)(m0 + r) * DD + k0 + c * 4);
            __half2 h01 = __floats2half2_rn(v.x, v.y);
            __half2 h23 = __floats2half2_rn(v.z, v.w);
            float2 f01 = __half22float2(h01);
            float2 f23 = __half22float2(h23);
            __half2 l01 = __floats2half2_rn(v.x - f01.x, v.y - f01.y);
            __half2 l23 = __floats2half2_rn(v.z - f23.x, v.w - f23.y);
            uint32_t so = sw128((uint32_t)(r * 128 + c * 8));
            *(__half2*)(stgp + OFF_A + so)     = h01;
            *(__half2*)(stgp + OFF_A + so + 4) = h23;
            uint32_t sl = sw128((uint32_t)(r * 128 + 64 + c * 8));
            *(__half2*)(stgp + OFF_A + sl)     = l01;
            *(__half2*)(stgp + OFF_A + sl + 4) = l23;
        }
        // ---- stage B: ALL 512 n-rows, two 32KB blocks (n-half 0 / 1)
        #pragma unroll
        for (int it = 0; it < 16; ++it) {
            int idx = tid + it * 256;          // 0..4095
            int n = idx >> 3, c = idx & 7;     // c<4: hi 16B chunks, c>=4: lo
            const __half* src = (c < 4)
                ? (g_w1t_h16 + (size_t)n * DD + k0 + c * 8)
                : (g_w1t_l16 + (size_t)n * DD + k0 + (c - 4) * 8);
            uint4 v = *(const uint4*)src;
            uint32_t dst = OFF_B + (n & 256 ? 32768 : 0)
                         + sw128((uint32_t)((n & 255) * 128 + c * 16));
            *(uint4*)(stgp + dst) = v;
        }
        FENCE_ASYNC();
        __syncthreads();

        if (wid == 4) {
            if (elect_one()) {
                uint64_t ad = make_sw128_desc(stg + OFF_A);
                #pragma unroll
                for (int nh = 0; nh < 2; ++nh) {
                    uint64_t bd = make_sw128_desc(stg + OFF_B + nh * 32768);
                    uint32_t dt = tmem_base + nh * 256;
                    #pragma unroll
                    for (int ks = 0; ks < 2; ++ks) {
                        uint32_t en = (chunk == 0 && ks == 0) ? 0u : 1u;
                        tc05_mma_f16_ss(dt, ad + ks * 2, bd + ks * 2, IDESC_F16, en);
                        tc05_mma_f16_ss(dt, ad + 4 + ks * 2, bd + ks * 2, IDESC_F16, 1u);
                        tc05_mma_f16_ss(dt, ad + ks * 2, bd + 4 + ks * 2, IDESC_F16, 1u);
                    }
                }
                TC05_COMMIT(mbar);
            }
        }
    }

    // ---- drain: each buffer had 12 uses; final completion -> parity wait 1
    #pragma unroll
    for (int k = 0; k < NBUF; ++k) MBAR_WAIT(sb + OFF_MBARS + 8 * k, 1);
    TC05_FENCE_AFTER();

    // ---- epilogue: warps 0-3 read n-half 0, warps 4-7 read n-half 1
    {
        const float* b1s = (const float*)(base + OFF_B1S);
        const float* w2s = (const float*)(base + OFF_W2S);
        float* red = (float*)(base + OFF_RED);
        const int half = wid >> 2;
        const int row = (wid & 3) * 32 + lane;
        float s = 0.f;
        const uint32_t dtb = tmem_base + half * 256;
        #pragma unroll
        for (int cb = 0; cb < 8; ++cb) {
            uint32_t d[32];
            TC05_LD_X32(d, dtb + cb * 32);
            TC05_WAIT_LD();
            #pragma unroll
            for (int c = 0; c < 32; ++c) {
                int n = half * 256 + cb * 32 + c;
                s += fmaxf(__uint_as_float(d[c]) + b1s[n], 0.f) * w2s[n];
            }
        }
        TC05_FENCE_BEFORE();
        red[row * 2 + half] = s;
        __syncthreads();
        if (tid < 128) {
            g_logits[m0 + tid] = red[tid * 2] + red[tid * 2 + 1] + b2[0];
        }
    }

    __syncthreads();
    if (wid == 0) {
        asm volatile("tcgen05.relinquish_alloc_permit.cta_group::1.sync.aligned;");
        asm volatile("tcgen05.dealloc.cta_group::1.sync.aligned.b32 %0, %1;"
                     :: "r"(tmem_base), "r"(512u));
    }
#endif // HAS_TC05
}

// ===========================================================================
// PATH B: mma.sync fallback (launched only if the tc05 kernel is a stub)
// ===========================================================================
#define MT 128
#define NT 128
#define KT 32
#define AS_STRIDE 36
#define BS_STRIDE 136

#if !HAS_TC05
__device__ __forceinline__ void mma_tf32(float* d, unsigned a0, unsigned a1,
                                         unsigned a2, unsigned a3,
                                         unsigned b0, unsigned b1) {
    asm volatile(
        "mma.sync.aligned.m16n8k8.row.col.f32.tf32.tf32.f32 "
        "{%0,%1,%2,%3}, {%4,%5,%6,%7}, {%8,%9}, {%0,%1,%2,%3};"
        : "+f"(d[0]), "+f"(d[1]), "+f"(d[2]), "+f"(d[3])
        : "r"(a0), "r"(a1), "r"(a2), "r"(a3), "r"(b0), "r"(b1));
}
#endif

__global__ __launch_bounds__(256) void gemm_logits_fb_kernel(
    const float* __restrict__ X,   // [NTOK, DD]
    const float* __restrict__ W1,  // [DD, HH]
    const float* __restrict__ b1,  // [HH]
    const float* __restrict__ W2,  // [HH]
    const float* __restrict__ b2)  // [1]
{
#if !HAS_TC05
    __shared__ float As2[MT][AS_STRIDE];
    __shared__ float Bs2[KT][BS_STRIDE];
    __shared__ float red[MT][4];

    const int tid = threadIdx.x;
    const int lane = tid & 31;
    const int wid = tid >> 5;
    const int warp_m = wid & 1;
    const int warp_n = wid >> 1;
    const int g = lane >> 2;
    const int t = lane & 3;
    const int m0 = blockIdx.x * MT;

    float s[4][2];
    #pragma unroll
    for (int mf = 0; mf < 4; ++mf) { s[mf][0] = 0.f; s[mf][1] = 0.f; }

    for (int nc = 0; nc < HH / NT; ++nc) {
        const int nbase = nc * NT;

        float acc[4][4][4];
        #pragma unroll
        for (int mf = 0; mf < 4; ++mf)
            #pragma unroll
            for (int nf = 0; nf < 4; ++nf)
                #pragma unroll
                for (int e = 0; e < 4; ++e) acc[mf][nf][e] = 0.f;

        for (int k0 = 0; k0 < DD; k0 += KT) {
            __syncthreads();
            #pragma unroll
            for (int it = 0; it < 4; ++it) {
                int idx = tid + it * 256;
                int row = idx >> 3, c4 = idx & 7;
                float4 v = *(const float4*)(X + (size_t)(m0 + row) * DD + k0 + c4 * 4);
                *(float4*)&As2[row][c4 * 4] = v;
            }
            #pragma unroll
            for (int it = 0; it < 4; ++it) {
                int idx = tid + it * 256;
                int row = idx >> 5, c4 = idx & 31;
                float4 v = *(const float4*)(W1 + (size_t)(k0 + row) * HH + nbase + c4 * 4);
                *(float4*)&Bs2[row][c4 * 4] = v;
            }
            __syncthreads();

            #pragma unroll
            for (int ks = 0; ks < KT / 8; ++ks) {
                const int kb = ks * 8;
                unsigned ahi[4][4], alo[4][4];
                #pragma unroll
                for (int mf = 0; mf < 4; ++mf) {
                    const int r = warp_m * 64 + mf * 16 + g;
                    float f0 = As2[r][kb + t];
                    float f1 = As2[r + 8][kb + t];
                    float f2 = As2[r][kb + t + 4];
                    float f3 = As2[r + 8][kb + t + 4];
                    ahi[mf][0] = cvt_tf32(f0);
                    ahi[mf][1] = cvt_tf32(f1);
                    ahi[mf][2] = cvt_tf32(f2);
                    ahi[mf][3] = cvt_tf32(f3);
                    alo[mf][0] = cvt_tf32(f0 - __uint_as_float(ahi[mf][0]));
                    alo[mf][1] = cvt_tf32(f1 - __uint_as_float(ahi[mf][1]));
                    alo[mf][2] = cvt_tf32(f2 - __uint_as_float(ahi[mf][2]));
                    alo[mf][3] = cvt_tf32(f3 - __uint_as_float(ahi[mf][3]));
                }
                #pragma unroll
                for (int nf = 0; nf < 4; ++nf) {
                    const int col = warp_n * 32 + nf * 8 + g;
                    float fb0 = Bs2[kb + t][col];
                    float fb1 = Bs2[kb + t + 4][col];
                    unsigned bhi0 = cvt_tf32(fb0);
                    unsigned bhi1 = cvt_tf32(fb1);
                    unsigned blo0 = cvt_tf32(fb0 - __uint_as_float(bhi0));
                    unsigned blo1 = cvt_tf32(fb1 - __uint_as_float(bhi1));
                    #pragma unroll
                    for (int mf = 0; mf < 4; ++mf) {
                        mma_tf32(acc[mf][nf], ahi[mf][0], ahi[mf][1], ahi[mf][2], ahi[mf][3], bhi0, bhi1);
                        mma_tf32(acc[mf][nf], alo[mf][0], alo[mf][1], alo[mf][2], alo[mf][3], bhi0, bhi1);
                        mma_tf32(acc[mf][nf], ahi[mf][0], ahi[mf][1], ahi[mf][2], ahi[mf][3], blo0, blo1);
                    }
                }
            }
        }

        #pragma unroll
        for (int nf = 0; nf < 4; ++nf) {
            const int c0 = nbase + warp_n * 32 + nf * 8 + t * 2;
            const float bb0 = b1[c0],     bb1 = b1[c0 + 1];
            const float w0  = W2[c0],     w1  = W2[c0 + 1];
            #pragma unroll
            for (int mf = 0; mf < 4; ++mf) {
                s[mf][0] += fmaxf(acc[mf][nf][0] + bb0, 0.f) * w0
                          + fmaxf(acc[mf][nf][1] + bb1, 0.f) * w1;
                s[mf][1] += fmaxf(acc[mf][nf][2] + bb0, 0.f) * w0
                          + fmaxf(acc[mf][nf][3] + bb1, 0.f) * w1;
            }
        }
    }

    #pragma unroll
    for (int mf = 0; mf < 4; ++mf) {
        #pragma unroll
        for (int h = 0; h < 2; ++h) {
            float v = s[mf][h];
            v += __shfl_down_sync(0xffffffffu, v, 1);
            v += __shfl_down_sync(0xffffffffu, v, 2);
            s[mf][h] = v;
        }
    }
    __syncthreads();
    if (t == 0) {
        #pragma unroll
        for (int mf = 0; mf < 4; ++mf) {
            const int r = warp_m * 64 + mf * 16 + g;
            red[r][warp_n] = s[mf][0];
            red[r + 8][warp_n] = s[mf][1];
        }
    }
    __syncthreads();
    if (tid < MT) {
        float v = red[tid][0] + red[tid][1] + red[tid][2] + red[tid][3];
        g_logits[m0 + tid] = v + b2[0];
    }
#endif // !HAS_TC05
}

// ---------------------------------------------------------------------------
// K2: per-batch boundary sample + scan + segment starts + fused scalars.
// ---------------------------------------------------------------------------
__global__ __launch_bounds__(1024) void scan_kernel(
    const float* __restrict__ noise_u, float* __restrict__ outs)
{
    const int b = blockIdx.x;
    const int tid = threadIdx.x;
    const int l0 = tid * 4;
    const int base = b * LL + l0;

    int hd[4];
    #pragma unroll
    for (int j = 0; j < 4; ++j) {
        float u = noise_u[base + j];
        float x = g_logits[base + j] + logf(u) - log1pf(-u);
        hd[j] = (x > 0.f) ? 1 : 0;
    }
    int p = hd[0] + hd[1] + hd[2] + hd[3];

    const int lane = tid & 31;
    const int warp = tid >> 5;
    int v = p;
    #pragma unroll
    for (int off = 1; off < 32; off <<= 1) {
        int n = __shfl_up_sync(0xffffffffu, v, off);
        if (lane >= off) v += n;
    }
    __shared__ int wsum[32];
    if (lane == 31) wsum[warp] = v;
    __syncthreads();
    if (warp == 0) {
        int w = wsum[lane];
        #pragma unroll
        for (int off = 1; off < 32; off <<= 1) {
            int n = __shfl_up_sync(0xffffffffu, w, off);
            if (lane >= off) w += n;
        }
        wsum[lane] = w;
    }
    __syncthreads();

    int excl = (warp ? wsum[warp - 1] : 0) + v - p;   // boundaries strictly before l0
    int run = excl;                                    // = seg id of current token
    if (tid == 0) g_segstart[b * LL] = 0;
    #pragma unroll
    for (int j = 0; j < 4; ++j) {
        if (hd[j]) {
            int nxt = l0 + j + 1;
            if (nxt < LL) g_segstart[b * LL + run + 1] = nxt;
        }
        run += hd[j];
    }
    if (tid == 1023) {
        g_bcnt[b] = run;
        g_nseg[b] = run - hd[3] + 1;
        __threadfence();
        int done = atomicAdd(&g_done, 1);
        if (done == BB - 1) {
            int nb = 0;
            #pragma unroll
            for (int i = 0; i < BB; ++i) nb += g_bcnt[i];
            float ratio = (float)nb / (float)NTOK;
            outs[0] = fmaxf(fabsf(ratio - 0.25f) - 0.05f, 0.f);
            outs[1] = (float)nb;
            outs[2] = (float)NTOK;
            atomicExch(&g_done, 0);
        }
    }
}

// ---------------------------------------------------------------------------
// K4: pooled output — one warp per OUTPUT row (b, s). Covers all rows.
// ---------------------------------------------------------------------------
__global__ __launch_bounds__(256) void pool_kernel(
    const float* __restrict__ hidden, float* __restrict__ out)
{
    const int gwarp = (blockIdx.x * blockDim.x + threadIdx.x) >> 5;
    const int lane = threadIdx.x & 31;
    const int b = gwarp >> 12;          // / LL
    const int s = gwarp & (LL - 1);     // % LL

    float4 acc[6];
    #pragma unroll
    for (int i = 0; i < 6; ++i) acc[i] = make_float4(0.f, 0.f, 0.f, 0.f);

    const int nseg = g_nseg[b];
    if (s < nseg) {
        const int start = g_segstart[b * LL + s];
        const int end = (s + 1 < nseg) ? g_segstart[b * LL + s + 1] : LL;
        const float4* row = (const float4*)(hidden + ((size_t)b * LL + start) * DD);
        #pragma unroll 2
        for (int j = start; j < end; ++j, row += DD / 4) {
            #pragma unroll
            for (int i = 0; i < 6; ++i) {
                float4 r = row[lane + 32 * i];
                acc[i].x += r.x; acc[i].y += r.y; acc[i].z += r.z; acc[i].w += r.w;
            }
        }
        const float inv = 1.0f / (float)(end - start);
        #pragma unroll
        for (int i = 0; i < 6; ++i) {
            acc[i].x *= inv; acc[i].y *= inv; acc[i].z *= inv; acc[i].w *= inv;
        }
    }

    float4* orow = (float4*)(out + ((size_t)b * LL + s) * DD);
    #pragma unroll
    for (int i = 0; i < 6; ++i) orow[lane + 32 * i] = acc[i];
}

// ---------------------------------------------------------------------------
extern "C" void kernel_launch(void* const* d_in, const int* in_sizes, int n_in,
                              void* d_out, int out_size) {
    const float* hidden  = (const float*)d_in[0];
    const float* W1      = (const float*)d_in[1];
    const float* b1      = (const float*)d_in[2];
    const float* W2      = (const float*)d_in[3];
    const float* b2      = (const float*)d_in[4];
    const float* noise_u = (const float*)d_in[5];
    float* out = (float*)d_out;

    // Which GEMM has a body in the loaded cubin? (host code runs at capture time)
    cudaFuncAttributes attr;
    cudaFuncGetAttributes(&attr, gemm_logits_tc05_kernel);
    const bool tc05_live = attr.numRegs > 24;

    if (tc05_live) {
        cudaFuncSetAttribute(gemm_logits_tc05_kernel,
                             cudaFuncAttributeMaxDynamicSharedMemorySize, SMEM_TOTAL);
        w1prep_kernel<<<(DD * HH) / 256, 256>>>(W1);
        gemm_logits_tc05_kernel<<<NTOK / 128, 256, SMEM_TOTAL>>>(hidden, b1, W2, b2);
    } else {
        gemm_logits_fb_kernel<<<NTOK / MT, 256>>>(hidden, W1, b1, W2, b2);
    }
    scan_kernel<<<BB, 1024>>>(noise_u, out + (out_size - 3));
    pool_kernel<<<NTOK / 8, 256>>>(hidden, out);
}

// round 14
// speedup vs baseline: 6.7516x; 1.2395x over previous
#include <cuda_runtime.h>
#include <cuda_bf16.h>
#include <cuda_fp16.h>
#include <math.h>
#include <stdint.h>

// Problem constants (fixed by the dataset)
#define BB 8
#define LL 4096
#define DD 768
#define HH 512
#define NTOK (BB * LL)          // 32768
#define POOLED_ELEMS (BB * LL * DD)

// Arch-specific feature gate (proven live on this bench in R6).
#if defined(__CUDA_ARCH__) && (defined(__CUDA_ARCH_FEAT_SM103_ALL) || \
    defined(__CUDA_ARCH_FEAT_SM100_ALL) || defined(__CUDA_ARCH_SPECIFIC__) || \
    defined(__CUDA_ARCH_FAMILY_SPECIFIC__))
#define HAS_TC05 1
#else
#define HAS_TC05 0
#endif

#define KC 32
#define NUM_CHUNK (DD / KC)      // 24
#define NBUF 2
#define BBLK 32768               // one pre-swizzled B n-half block (256 rows x 128B)

// Device scratch (no allocations allowed)
__device__ float         g_logits[NTOK];
__device__ int           g_segstart[NTOK];   // per batch: start token of segment s
__device__ int           g_nseg[BB];
__device__ int           g_bcnt[BB];
__device__ int           g_done;             // scan completion counter (self-resetting)
// Pre-swizzled B tiles: [chunk][nhalf][32KB], byte-exact SMEM SW128 layout.
// Row n (0..255): [f16(w) x32 | f16(w - f16(w)) x32], swizzled.
__device__ __align__(128) unsigned char g_w1s[NUM_CHUNK * 2 * BBLK];

// ---------------------------------------------------------------------------
// Common helpers
// ---------------------------------------------------------------------------
__device__ __forceinline__ unsigned cvt_tf32(float f) {
    unsigned r;
    asm("cvt.rna.tf32.f32 %0, %1;" : "=r"(r) : "f"(f));
    return r;
}
__device__ __forceinline__ uint32_t smem_u32(const void* p) {
    uint32_t a;
    asm("{ .reg .u64 t; cvta.to.shared.u64 t, %1; cvt.u32.u64 %0, t; }" : "=r"(a) : "l"(p));
    return a;
}
__device__ __forceinline__ uint32_t sw128(uint32_t off) {
    return off ^ ((off >> 3) & 0x70);
}

// ---------------------------------------------------------------------------
// K-pre (tcgen05 path only): W1 [DD,HH] -> pre-swizzled f16 hi/lo tile blocks.
// One thread per 16-byte output chunk (98304 threads).
// ---------------------------------------------------------------------------
__global__ __launch_bounds__(256) void w1prep_kernel(const float* __restrict__ W1) {
#if HAS_TC05
    int idx = blockIdx.x * 256 + threadIdx.x;      // 0..98303
    int chunk = idx >> 12;                         // 24 chunks
    int q = idx & 4095;
    int n = q >> 3;                                // 0..511 (global hidden unit)
    int c = q & 7;                                 // c<4: hi groups, c>=4: lo
    int h = n >> 8;                                // n-half
    int nn = n & 255;
    int k0 = chunk * KC + (c & 3) * 8;

    __half out[8];
    #pragma unroll
    for (int j = 0; j < 8; ++j) {
        float w = W1[(size_t)(k0 + j) * HH + n];
        __half hi = __float2half_rn(w);
        out[j] = (c < 4) ? hi : __float2half_rn(w - __half2float(hi));
    }
    unsigned char* dst = g_w1s + ((size_t)(chunk * 2 + h)) * BBLK
                       + sw128((uint32_t)(nn * 128 + c * 16));
    *(uint4*)dst = *(const uint4*)out;
#endif
}

// ===========================================================================
// PATH A: tcgen05 GEMM, f16x3 split. Per CTA: M=128, N=512 in a SINGLE
// K-sweep (TMEM: nh0 -> cols 0-255, nh1 -> cols 256-511), K-chunk 32.
// B staged via cp.async.bulk from pre-swizzled blocks (full/empty barriers);
// A staged thread-side with fp32->f16 hi/lo conversion. One epilogue.
// ===========================================================================
#define OFF_TMEMPTR 0
#define OFF_MBARS   16           // empty[2] at +0,+8 ; full[2] at +16,+24
#define OFF_B1S     64
#define OFF_W2S     (64 + 2048)
#define OFF_RED     4224         // 128 rows x 2 halves x 4B
#define OFF_STAGE   6144
#define OFF_A       0
#define OFF_B       16384        // two 32KB n-half blocks
#define STAGE_SZ    81920
#define SMEM_TOTAL  (OFF_STAGE + NBUF * STAGE_SZ + 1024)

#if HAS_TC05
__device__ __forceinline__ uint32_t elect_one() {
    uint32_t p;
    asm volatile("{\n\t.reg .pred p;\n\telect.sync _|p, 0xFFFFFFFF;\n\tselp.b32 %0, 1, 0, p;\n\t}" : "=r"(p));
    return p;
}
__device__ __forceinline__ uint64_t make_sw128_desc(uint32_t addr) {
    const uint64_t base = (2ull << 61) | (1ull << 46) | (64ull << 32) | (1ull << 16);
    return base | ((uint64_t)(addr >> 4) & 0x3FFF);
}
__device__ __forceinline__ void tc05_mma_f16_ss(uint32_t d_tmem, uint64_t a_desc,
                                                uint64_t b_desc, uint32_t idesc,
                                                uint32_t enable) {
    asm volatile(
        "{\n\t.reg .pred p;\n\tsetp.ne.u32 p, %5, 0;\n\t"
        "tcgen05.mma.cta_group::1.kind::f16 [%0], %1, %2, %3, {%4, %4, %4, %4}, p;\n\t}"
        :: "r"(d_tmem), "l"(a_desc), "l"(b_desc), "r"(idesc), "r"(0u), "r"(enable)
        : "memory");
}
#define MBAR_INIT(addr, cnt) \
    asm volatile("mbarrier.init.shared.b64 [%0], %1;" :: "r"(addr), "r"(cnt) : "memory")
#define MBAR_EXPECT_TX(addr, tx) \
    asm volatile("mbarrier.arrive.expect_tx.shared.b64 _, [%0], %1;" \
                 :: "r"(addr), "r"(tx) : "memory")
#define BULK_G2S(dst, src, bytes, mbar) \
    asm volatile("cp.async.bulk.shared::cta.global.mbarrier::complete_tx::bytes " \
                 "[%0], [%1], %2, [%3];" \
                 :: "r"(dst), "l"(src), "r"(bytes), "r"(mbar) : "memory")
#define TC05_COMMIT(addr) \
    asm volatile("tcgen05.commit.cta_group::1.mbarrier::arrive::one.shared::cluster.b64 [%0];" \
                 :: "r"(addr) : "memory")
#define MBAR_WAIT(addr, ph) do {                                                   \
    uint32_t _m = (addr), _p = (ph), _d;                                           \
    asm volatile("{\n\t.reg .pred p;\n\t"                                          \
        "mbarrier.try_wait.parity.acquire.cta.shared::cta.b64 p, [%1], %2;\n\t"    \
        "selp.b32 %0, 1, 0, p;\n\t}" : "=r"(_d) : "r"(_m), "r"(_p) : "memory");    \
    if (!_d) {                                                                     \
        asm volatile("{\n\t.reg .pred P1;\n\t"                                     \
            "W_%=:\n\t"                                                            \
            "mbarrier.try_wait.parity.acquire.cta.shared::cta.b64 P1, [%0], %1, 0x989680;\n\t" \
            "@P1 bra.uni D_%=;\n\tbra.uni W_%=;\n\tD_%=:\n\t}"                     \
            :: "r"(_m), "r"(_p) : "memory");                                       \
    } } while (0)
#define FENCE_ASYNC() asm volatile("fence.proxy.async.shared::cta;" ::: "memory")
#define TC05_FENCE_AFTER() asm volatile("tcgen05.fence::after_thread_sync;" ::: "memory")
#define TC05_FENCE_BEFORE() asm volatile("tcgen05.fence::before_thread_sync;" ::: "memory")
#define TC05_WAIT_LD() asm volatile("tcgen05.wait::ld.sync.aligned;" ::: "memory")
#define TC05_LD_X32(r, a)                                                          \
    asm volatile("tcgen05.ld.sync.aligned.32x32b.x32.b32 "                         \
        "{%0, %1, %2, %3, %4, %5, %6, %7, %8, %9, %10, %11, %12, %13, %14, %15, "  \
        " %16, %17, %18, %19, %20, %21, %22, %23, %24, %25, %26, %27, %28, %29, %30, %31}, [%32];" \
        : "=r"((r)[0]), "=r"((r)[1]), "=r"((r)[2]), "=r"((r)[3]),                  \
          "=r"((r)[4]), "=r"((r)[5]), "=r"((r)[6]), "=r"((r)[7]),                  \
          "=r"((r)[8]), "=r"((r)[9]), "=r"((r)[10]), "=r"((r)[11]),                \
          "=r"((r)[12]), "=r"((r)[13]), "=r"((r)[14]), "=r"((r)[15]),              \
          "=r"((r)[16]), "=r"((r)[17]), "=r"((r)[18]), "=r"((r)[19]),              \
          "=r"((r)[20]), "=r"((r)[21]), "=r"((r)[22]), "=r"((r)[23]),              \
          "=r"((r)[24]), "=r"((r)[25]), "=r"((r)[26]), "=r"((r)[27]),              \
          "=r"((r)[28]), "=r"((r)[29]), "=r"((r)[30]), "=r"((r)[31])               \
        : "r"(a))

// idesc: dtype F32, atype/btype F16(0), N=256, M=128
#define IDESC_F16  ((1u << 4) | ((256 / 8) << 17) | ((128 / 16) << 24))
#endif // HAS_TC05

__global__ __launch_bounds__(256, 1)
void gemm_logits_tc05_kernel(
    const float* __restrict__ X,   // [NTOK, DD]
    const float* __restrict__ b1,  // [HH]
    const float* __restrict__ W2,  // [HH]
    const float* __restrict__ b2)  // [1]
{
#if HAS_TC05
    extern __shared__ char dsm[];
    const uint32_t smem_raw = smem_u32(dsm);
    const uint32_t sb = (smem_raw + 1023u) & ~1023u;
    char* base = dsm + (sb - smem_raw);
    const int tid = threadIdx.x;
    const int lane = tid & 31;
    const int wid = tid >> 5;
    const int m0 = blockIdx.x * 128;

    if (wid == 0) {
        asm volatile("tcgen05.alloc.cta_group::1.sync.aligned.shared::cta.b32 [%0], %1;"
                     :: "r"(sb + OFF_TMEMPTR), "r"(512u) : "memory");
    }
    if (tid == 0) {
        #pragma unroll
        for (int k = 0; k < NBUF; ++k) {
            MBAR_INIT(sb + OFF_MBARS + 8 * k, 1);        // empty[k]
            MBAR_INIT(sb + OFF_MBARS + 16 + 8 * k, 1);   // full[k]
        }
    }
    for (int i = tid; i < HH; i += 256) {
        *(float*)(base + OFF_B1S + i * 4) = b1[i];
        *(float*)(base + OFF_W2S + i * 4) = W2[i];
    }
    __syncthreads();
    uint32_t tmem_base;
    asm volatile("ld.shared.b32 %0, [%1];" : "=r"(tmem_base) : "r"(sb + OFF_TMEMPTR));

    for (int chunk = 0; chunk < NUM_CHUNK; ++chunk) {
        const int buf = chunk & 1;
        const int u = chunk >> 1;              // use index of this buffer
        const int k0 = chunk * KC;
        char* stgp = base + OFF_STAGE + buf * STAGE_SZ;
        const uint32_t stg = sb + OFF_STAGE + buf * STAGE_SZ;
        const uint32_t mbar_e = sb + OFF_MBARS + 8 * buf;
        const uint32_t mbar_f = sb + OFF_MBARS + 16 + 8 * buf;

        // wait until MMAs of this buffer's previous use completed
        if (chunk >= NBUF) MBAR_WAIT(mbar_e, (u - 1) & 1);

        // ---- B: one elected thread kicks 2 x 32KB bulk copies (pre-swizzled)
        if (wid == 5) {
            if (elect_one()) {
                MBAR_EXPECT_TX(mbar_f, 2 * BBLK);
                const unsigned char* src = g_w1s + (size_t)(chunk * 2) * BBLK;
                BULK_G2S(stg + OFF_B, src, BBLK, mbar_f);
                BULK_G2S(stg + OFF_B + BBLK, src + BBLK, BBLK, mbar_f);
            }
        }

        // ---- stage A: one M tile, rows [h(a)x32 | h(alo)x32] (128B, SW128)
        #pragma unroll
        for (int it = 0; it < 4; ++it) {
            int idx = tid + it * 256;          // 0..1023
            int r = idx >> 3;
            int c = idx & 7;
            float4 v = *(const float4*)(X + (size_t)(m0 + r) * DD + k0 + c * 4);
            __half2 h01 = __floats2half2_rn(v.x, v.y);
            __half2 h23 = __floats2half2_rn(v.z, v.w);
            float2 f01 = __half22float2(h01);
            float2 f23 = __half22float2(h23);
            __half2 l01 = __floats2half2_rn(v.x - f01.x, v.y - f01.y);
            __half2 l23 = __floats2half2_rn(v.z - f23.x, v.w - f23.y);
            uint32_t so = sw128((uint32_t)(r * 128 + c * 8));
            *(__half2*)(stgp + OFF_A + so)     = h01;
            *(__half2*)(stgp + OFF_A + so + 4) = h23;
            uint32_t sl = sw128((uint32_t)(r * 128 + 64 + c * 8));
            *(__half2*)(stgp + OFF_A + sl)     = l01;
            *(__half2*)(stgp + OFF_A + sl + 4) = l23;
        }
        FENCE_ASYNC();
        __syncthreads();

        if (wid == 4) {
            MBAR_WAIT(mbar_f, u & 1);          // B tile delivered
            if (elect_one()) {
                uint64_t ad = make_sw128_desc(stg + OFF_A);
                #pragma unroll
                for (int nh = 0; nh < 2; ++nh) {
                    uint64_t bd = make_sw128_desc(stg + OFF_B + nh * BBLK);
                    uint32_t dt = tmem_base + nh * 256;
                    #pragma unroll
                    for (int ks = 0; ks < 2; ++ks) {
                        uint32_t en = (chunk == 0 && ks == 0) ? 0u : 1u;
                        tc05_mma_f16_ss(dt, ad + ks * 2, bd + ks * 2, IDESC_F16, en);
                        tc05_mma_f16_ss(dt, ad + 4 + ks * 2, bd + ks * 2, IDESC_F16, 1u);
                        tc05_mma_f16_ss(dt, ad + ks * 2, bd + 4 + ks * 2, IDESC_F16, 1u);
                    }
                }
                TC05_COMMIT(mbar_e);
            }
        }
    }

    // ---- drain: each buffer had 12 uses; final completion -> parity wait 1
    #pragma unroll
    for (int k = 0; k < NBUF; ++k) MBAR_WAIT(sb + OFF_MBARS + 8 * k, 1);
    TC05_FENCE_AFTER();

    // ---- epilogue: warps 0-3 read n-half 0, warps 4-7 read n-half 1
    {
        const float* b1s = (const float*)(base + OFF_B1S);
        const float* w2s = (const float*)(base + OFF_W2S);
        float* red = (float*)(base + OFF_RED);
        const int half = wid >> 2;
        const int row = (wid & 3) * 32 + lane;
        float s = 0.f;
        const uint32_t dtb = tmem_base + half * 256;
        #pragma unroll
        for (int cb = 0; cb < 8; ++cb) {
            uint32_t d[32];
            TC05_LD_X32(d, dtb + cb * 32);
            TC05_WAIT_LD();
            #pragma unroll
            for (int c = 0; c < 32; ++c) {
                int n = half * 256 + cb * 32 + c;
                s += fmaxf(__uint_as_float(d[c]) + b1s[n], 0.f) * w2s[n];
            }
        }
        TC05_FENCE_BEFORE();
        red[row * 2 + half] = s;
        __syncthreads();
        if (tid < 128) {
            g_logits[m0 + tid] = red[tid * 2] + red[tid * 2 + 1] + b2[0];
        }
    }

    __syncthreads();
    if (wid == 0) {
        asm volatile("tcgen05.relinquish_alloc_permit.cta_group::1.sync.aligned;");
        asm volatile("tcgen05.dealloc.cta_group::1.sync.aligned.b32 %0, %1;"
                     :: "r"(tmem_base), "r"(512u));
    }
#endif // HAS_TC05
}

// ===========================================================================
// PATH B: mma.sync fallback (launched only if the tc05 kernel is a stub)
// ===========================================================================
#define MT 128
#define NT 128
#define KT 32
#define AS_STRIDE 36
#define BS_STRIDE 136

#if !HAS_TC05
__device__ __forceinline__ void mma_tf32(float* d, unsigned a0, unsigned a1,
                                         unsigned a2, unsigned a3,
                                         unsigned b0, unsigned b1) {
    asm volatile(
        "mma.sync.aligned.m16n8k8.row.col.f32.tf32.tf32.f32 "
        "{%0,%1,%2,%3}, {%4,%5,%6,%7}, {%8,%9}, {%0,%1,%2,%3};"
        : "+f"(d[0]), "+f"(d[1]), "+f"(d[2]), "+f"(d[3])
        : "r"(a0), "r"(a1), "r"(a2), "r"(a3), "r"(b0), "r"(b1));
}
#endif

__global__ __launch_bounds__(256) void gemm_logits_fb_kernel(
    const float* __restrict__ X,   // [NTOK, DD]
    const float* __restrict__ W1,  // [DD, HH]
    const float* __restrict__ b1,  // [HH]
    const float* __restrict__ W2,  // [HH]
    const float* __restrict__ b2)  // [1]
{
#if !HAS_TC05
    __shared__ float As2[MT][AS_STRIDE];
    __shared__ float Bs2[KT][BS_STRIDE];
    __shared__ float red[MT][4];

    const int tid = threadIdx.x;
    const int lane = tid & 31;
    const int wid = tid >> 5;
    const int warp_m = wid & 1;
    const int warp_n = wid >> 1;
    const int g = lane >> 2;
    const int t = lane & 3;
    const int m0 = blockIdx.x * MT;

    float s[4][2];
    #pragma unroll
    for (int mf = 0; mf < 4; ++mf) { s[mf][0] = 0.f; s[mf][1] = 0.f; }

    for (int nc = 0; nc < HH / NT; ++nc) {
        const int nbase = nc * NT;

        float acc[4][4][4];
        #pragma unroll
        for (int mf = 0; mf < 4; ++mf)
            #pragma unroll
            for (int nf = 0; nf < 4; ++nf)
                #pragma unroll
                for (int e = 0; e < 4; ++e) acc[mf][nf][e] = 0.f;

        for (int k0 = 0; k0 < DD; k0 += KT) {
            __syncthreads();
            #pragma unroll
            for (int it = 0; it < 4; ++it) {
                int idx = tid + it * 256;
                int row = idx >> 3, c4 = idx & 7;
                float4 v = *(const float4*)(X + (size_t)(m0 + row) * DD + k0 + c4 * 4);
                *(float4*)&As2[row][c4 * 4] = v;
            }
            #pragma unroll
            for (int it = 0; it < 4; ++it) {
                int idx = tid + it * 256;
                int row = idx >> 5, c4 = idx & 31;
                float4 v = *(const float4*)(W1 + (size_t)(k0 + row) * HH + nbase + c4 * 4);
                *(float4*)&Bs2[row][c4 * 4] = v;
            }
            __syncthreads();

            #pragma unroll
            for (int ks = 0; ks < KT / 8; ++ks) {
                const int kb = ks * 8;
                unsigned ahi[4][4], alo[4][4];
                #pragma unroll
                for (int mf = 0; mf < 4; ++mf) {
                    const int r = warp_m * 64 + mf * 16 + g;
                    float f0 = As2[r][kb + t];
                    float f1 = As2[r + 8][kb + t];
                    float f2 = As2[r][kb + t + 4];
                    float f3 = As2[r + 8][kb + t + 4];
                    ahi[mf][0] = cvt_tf32(f0);
                    ahi[mf][1] = cvt_tf32(f1);
                    ahi[mf][2] = cvt_tf32(f2);
                    ahi[mf][3] = cvt_tf32(f3);
                    alo[mf][0] = cvt_tf32(f0 - __uint_as_float(ahi[mf][0]));
                    alo[mf][1] = cvt_tf32(f1 - __uint_as_float(ahi[mf][1]));
                    alo[mf][2] = cvt_tf32(f2 - __uint_as_float(ahi[mf][2]));
                    alo[mf][3] = cvt_tf32(f3 - __uint_as_float(ahi[mf][3]));
                }
                #pragma unroll
                for (int nf = 0; nf < 4; ++nf) {
                    const int col = warp_n * 32 + nf * 8 + g;
                    float fb0 = Bs2[kb + t][col];
                    float fb1 = Bs2[kb + t + 4][col];
                    unsigned bhi0 = cvt_tf32(fb0);
                    unsigned bhi1 = cvt_tf32(fb1);
                    unsigned blo0 = cvt_tf32(fb0 - __uint_as_float(bhi0));
                    unsigned blo1 = cvt_tf32(fb1 - __uint_as_float(bhi1));
                    #pragma unroll
                    for (int mf = 0; mf < 4; ++mf) {
                        mma_tf32(acc[mf][nf], ahi[mf][0], ahi[mf][1], ahi[mf][2], ahi[mf][3], bhi0, bhi1);
                        mma_tf32(acc[mf][nf], alo[mf][0], alo[mf][1], alo[mf][2], alo[mf][3], bhi0, bhi1);
                        mma_tf32(acc[mf][nf], ahi[mf][0], ahi[mf][1], ahi[mf][2], ahi[mf][3], blo0, blo1);
                    }
                }
            }
        }

        #pragma unroll
        for (int nf = 0; nf < 4; ++nf) {
            const int c0 = nbase + warp_n * 32 + nf * 8 + t * 2;
            const float bb0 = b1[c0],     bb1 = b1[c0 + 1];
            const float w0  = W2[c0],     w1  = W2[c0 + 1];
            #pragma unroll
            for (int mf = 0; mf < 4; ++mf) {
                s[mf][0] += fmaxf(acc[mf][nf][0] + bb0, 0.f) * w0
                          + fmaxf(acc[mf][nf][1] + bb1, 0.f) * w1;
                s[mf][1] += fmaxf(acc[mf][nf][2] + bb0, 0.f) * w0
                          + fmaxf(acc[mf][nf][3] + bb1, 0.f) * w1;
            }
        }
    }

    #pragma unroll
    for (int mf = 0; mf < 4; ++mf) {
        #pragma unroll
        for (int h = 0; h < 2; ++h) {
            float v = s[mf][h];
            v += __shfl_down_sync(0xffffffffu, v, 1);
            v += __shfl_down_sync(0xffffffffu, v, 2);
            s[mf][h] = v;
        }
    }
    __syncthreads();
    if (t == 0) {
        #pragma unroll
        for (int mf = 0; mf < 4; ++mf) {
            const int r = warp_m * 64 + mf * 16 + g;
            red[r][warp_n] = s[mf][0];
            red[r + 8][warp_n] = s[mf][1];
        }
    }
    __syncthreads();
    if (tid < MT) {
        float v = red[tid][0] + red[tid][1] + red[tid][2] + red[tid][3];
        g_logits[m0 + tid] = v + b2[0];
    }
#endif // !HAS_TC05
}

// ---------------------------------------------------------------------------
// K2: per-batch boundary sample + scan + segment starts + fused scalars.
// ---------------------------------------------------------------------------
__global__ __launch_bounds__(1024) void scan_kernel(
    const float* __restrict__ noise_u, float* __restrict__ outs)
{
    const int b = blockIdx.x;
    const int tid = threadIdx.x;
    const int l0 = tid * 4;
    const int base = b * LL + l0;

    int hd[4];
    #pragma unroll
    for (int j = 0; j < 4; ++j) {
        float u = noise_u[base + j];
        float x = g_logits[base + j] + logf(u) - log1pf(-u);
        hd[j] = (x > 0.f) ? 1 : 0;
    }
    int p = hd[0] + hd[1] + hd[2] + hd[3];

    const int lane = tid & 31;
    const int warp = tid >> 5;
    int v = p;
    #pragma unroll
    for (int off = 1; off < 32; off <<= 1) {
        int n = __shfl_up_sync(0xffffffffu, v, off);
        if (lane >= off) v += n;
    }
    __shared__ int wsum[32];
    if (lane == 31) wsum[warp] = v;
    __syncthreads();
    if (warp == 0) {
        int w = wsum[lane];
        #pragma unroll
        for (int off = 1; off < 32; off <<= 1) {
            int n = __shfl_up_sync(0xffffffffu, w, off);
            if (lane >= off) w += n;
        }
        wsum[lane] = w;
    }
    __syncthreads();

    int excl = (warp ? wsum[warp - 1] : 0) + v - p;   // boundaries strictly before l0
    int run = excl;                                    // = seg id of current token
    if (tid == 0) g_segstart[b * LL] = 0;
    #pragma unroll
    for (int j = 0; j < 4; ++j) {
        if (hd[j]) {
            int nxt = l0 + j + 1;
            if (nxt < LL) g_segstart[b * LL + run + 1] = nxt;
        }
        run += hd[j];
    }
    if (tid == 1023) {
        g_bcnt[b] = run;
        g_nseg[b] = run - hd[3] + 1;
        __threadfence();
        int done = atomicAdd(&g_done, 1);
        if (done == BB - 1) {
            int nb = 0;
            #pragma unroll
            for (int i = 0; i < BB; ++i) nb += g_bcnt[i];
            float ratio = (float)nb / (float)NTOK;
            outs[0] = fmaxf(fabsf(ratio - 0.25f) - 0.05f, 0.f);
            outs[1] = (float)nb;
            outs[2] = (float)NTOK;
            atomicExch(&g_done, 0);
        }
    }
}

// ---------------------------------------------------------------------------
// K4: pooled output — one warp per OUTPUT row (b, s). Covers all rows.
// 128-thread blocks for finer scheduling granularity (long-segment tail).
// ---------------------------------------------------------------------------
__global__ __launch_bounds__(128) void pool_kernel(
    const float* __restrict__ hidden, float* __restrict__ out)
{
    const int gwarp = (blockIdx.x * blockDim.x + threadIdx.x) >> 5;
    const int lane = threadIdx.x & 31;
    const int b = gwarp >> 12;          // / LL
    const int s = gwarp & (LL - 1);     // % LL

    float4 acc[6];
    #pragma unroll
    for (int i = 0; i < 6; ++i) acc[i] = make_float4(0.f, 0.f, 0.f, 0.f);

    const int nseg = g_nseg[b];
    if (s < nseg) {
        const int start = g_segstart[b * LL + s];
        const int end = (s + 1 < nseg) ? g_segstart[b * LL + s + 1] : LL;
        const float4* row = (const float4*)(hidden + ((size_t)b * LL + start) * DD);
        #pragma unroll 2
        for (int j = start; j < end; ++j, row += DD / 4) {
            #pragma unroll
            for (int i = 0; i < 6; ++i) {
                float4 r = row[lane + 32 * i];
                acc[i].x += r.x; acc[i].y += r.y; acc[i].z += r.z; acc[i].w += r.w;
            }
        }
        const float inv = 1.0f / (float)(end - start);
        #pragma unroll
        for (int i = 0; i < 6; ++i) {
            acc[i].x *= inv; acc[i].y *= inv; acc[i].z *= inv; acc[i].w *= inv;
        }
    }

    float4* orow = (float4*)(out + ((size_t)b * LL + s) * DD);
    #pragma unroll
    for (int i = 0; i < 6; ++i) orow[lane + 32 * i] = acc[i];
}

// ---------------------------------------------------------------------------
extern "C" void kernel_launch(void* const* d_in, const int* in_sizes, int n_in,
                              void* d_out, int out_size) {
    const float* hidden  = (const float*)d_in[0];
    const float* W1      = (const float*)d_in[1];
    const float* b1      = (const float*)d_in[2];
    const float* W2      = (const float*)d_in[3];
    const float* b2      = (const float*)d_in[4];
    const float* noise_u = (const float*)d_in[5];
    float* out = (float*)d_out;

    // Which GEMM has a body in the loaded cubin? (host code runs at capture time)
    cudaFuncAttributes attr;
    cudaFuncGetAttributes(&attr, gemm_logits_tc05_kernel);
    const bool tc05_live = attr.numRegs > 24;

    if (tc05_live) {
        cudaFuncSetAttribute(gemm_logits_tc05_kernel,
                             cudaFuncAttributeMaxDynamicSharedMemorySize, SMEM_TOTAL);
        w1prep_kernel<<<(NUM_CHUNK * 2 * BBLK / 16) / 256, 256>>>(W1);
        gemm_logits_tc05_kernel<<<NTOK / 128, 256, SMEM_TOTAL>>>(hidden, b1, W2, b2);
    } else {
        gemm_logits_fb_kernel<<<NTOK / MT, 256>>>(hidden, W1, b1, W2, b2);
    }
    scan_kernel<<<BB, 1024>>>(noise_u, out + (out_size - 3));
    pool_kernel<<<NTOK / 4, 128>>>(hidden, out);
}